// round 11
// baseline (speedup 1.0000x reference)
#include <cuda_runtime.h>
#include <cuda.h>
#include <cuda_bf16.h>
#include <cstdint>
#include <math.h>

#define BATCH 16384
#define OUTC  523   // 7 + 4 + 512

// ========================= PTX helpers (baseline sm_90-level, no arch-suffix) =========================
__device__ __forceinline__ uint32_t smem_u32(const void* p) {
    uint32_t a;
    asm("{ .reg .u64 t; cvta.to.shared.u64 t, %1; cvt.u32.u64 %0, t; }" : "=r"(a) : "l"(p));
    return a;
}
__device__ __forceinline__ void ldmx4(uint32_t& r0, uint32_t& r1, uint32_t& r2, uint32_t& r3, uint32_t addr) {
    asm volatile("ldmatrix.sync.aligned.m8n8.x4.shared.b16 {%0,%1,%2,%3}, [%4];"
                 : "=r"(r0), "=r"(r1), "=r"(r2), "=r"(r3) : "r"(addr));
}
__device__ __forceinline__ void mma16816(float* c, const uint32_t* a, uint32_t b0, uint32_t b1) {
    asm volatile("mma.sync.aligned.m16n8k16.row.col.f32.bf16.bf16.f32 "
                 "{%0,%1,%2,%3}, {%4,%5,%6,%7}, {%8,%9}, {%0,%1,%2,%3};"
                 : "+f"(c[0]), "+f"(c[1]), "+f"(c[2]), "+f"(c[3])
                 : "r"(a[0]), "r"(a[1]), "r"(a[2]), "r"(a[3]), "r"(b0), "r"(b1));
}
// SW64 swizzle: atom = 8 rows x 64B; conflict-free ldmatrix for 64B-row tiles
__device__ __forceinline__ uint32_t swz64(uint32_t off) { return off ^ ((off >> 3) & 0x30); }

__device__ __forceinline__ void tma2d(uint32_t dst, const CUtensorMap* map, int cx, int cy, uint32_t mbar) {
    asm volatile("cp.async.bulk.tensor.2d.shared::cta.global.tile.mbarrier::complete_tx::bytes "
                 "[%0], [%1, {%2, %3}], [%4];"
                 :: "r"(dst), "l"(map), "r"(cx), "r"(cy), "r"(mbar) : "memory");
}
#define MBARRIER_INIT(addr, cnt) \
    asm volatile("mbarrier.init.shared.b64 [%0], %1;" :: "r"((uint32_t)(addr)), "r"((uint32_t)(cnt)) : "memory")
#define MBARRIER_ARRIVE(addr) \
    asm volatile("mbarrier.arrive.shared.b64 _, [%0];" :: "r"((uint32_t)(addr)) : "memory")
#define MBARRIER_EXPECT_TX(addr, bytes) \
    asm volatile("mbarrier.arrive.expect_tx.shared.b64 _, [%0], %1;" \
        :: "r"((uint32_t)(addr)), "r"((uint32_t)(bytes)) : "memory")
#define MBARRIER_WAIT_PARITY(mbar_smem_addr, phase_parity) do { \
    uint32_t _mbar = (uint32_t)(mbar_smem_addr); \
    uint32_t _parity = (uint32_t)(phase_parity); \
    uint32_t _done; \
    asm volatile("{\n\t.reg .pred p;\n\t" \
        "mbarrier.try_wait.parity.acquire.cta.shared::cta.b64 p, [%1], %2;\n\t" \
        "selp.b32 %0, 1, 0, p;\n\t}" : "=r"(_done) : "r"(_mbar), "r"(_parity) : "memory"); \
    if (!_done) { \
        asm volatile("{\n\t.reg .pred P1;\n\t" \
            "WAIT_LOOP_%=:\n\t" \
            "mbarrier.try_wait.parity.acquire.cta.shared::cta.b64 P1, [%0], %1, 0x989680;\n\t" \
            "@P1 bra.uni WAIT_DONE_%=;\n\t" \
            "bra.uni WAIT_LOOP_%=;\n\t" \
            "WAIT_DONE_%=:\n\t}" :: "r"(_mbar), "r"(_parity) : "memory"); \
    } \
} while(0)

// ========================= scratch =========================
__device__ __align__(1024) __nv_bfloat16 g_xhi[BATCH * 1024];
__device__ __align__(1024) __nv_bfloat16 g_xlo[BATCH * 1024];
__device__ __align__(1024) __nv_bfloat16 g_y1hi[BATCH * 1024];
__device__ __align__(1024) __nv_bfloat16 g_y1lo[BATCH * 1024];
__device__ __align__(1024) __nv_bfloat16 g_d1hi[BATCH * 1024];
__device__ __align__(1024) __nv_bfloat16 g_d1lo[BATCH * 1024];
__device__ __align__(1024) __nv_bfloat16 g_z1hi[BATCH * 1024];   // bucket order
__device__ __align__(1024) __nv_bfloat16 g_z1lo[BATCH * 1024];
__device__ __align__(1024) __nv_bfloat16 g_z2hi[BATCH * 1024];   // bucket order
__device__ __align__(1024) __nv_bfloat16 g_z2lo[BATCH * 1024];
__device__ __align__(1024) __nv_bfloat16 g_t1hi[BATCH * 256];
__device__ __align__(1024) __nv_bfloat16 g_t1lo[BATCH * 256];
__device__ float g_fy[BATCH * 1024];
__device__ float g_fd[BATCH * 1024];
__device__ float g_ft[BATCH * 256];
__device__ __align__(1024) __nv_bfloat16 g_whi[10300000];
__device__ __align__(1024) __nv_bfloat16 g_wlo[10300000];
__device__ int g_ridx[BATCH];
__device__ int g_pos[BATCH];
__device__ int g_cnt[8];
__device__ int g_off[8];

// weight-pool offsets (elements)
#define OFF_TW1 0             // [256,256]
#define OFF_L1  65536         // [3328,1024]: yw0|dw0|zw0'|tw0
#define OFF_YW1 3473408
#define OFF_DW1 4521984
#define OFF_ZW1 5570560
#define OFF_ZHW 6619136       // [3584,1024]

__device__ __forceinline__ float elu_f(float v) { return v > 0.f ? v : expm1f(v); }
__device__ __forceinline__ float softplus_f(float v) {
    return fmaxf(v, 0.f) + log1pf(expf(-fabsf(v)));
}

// ========================= fused bucketing =========================
__global__ void bucket_all(const int* __restrict__ t) {
    __shared__ int scnt[8];
    __shared__ int scur[8];
    int tid = threadIdx.x;
    if (tid < 8) scnt[tid] = 0;
    __syncthreads();
    for (int i = tid; i < BATCH; i += 1024) atomicAdd(&scnt[t[i]], 1);
    __syncthreads();
    if (tid == 0) {
        int s = 0;
        for (int k = 0; k < 7; k++) { g_cnt[k] = scnt[k]; g_off[k] = s; scur[k] = s; s += scnt[k]; }
    }
    __syncthreads();
    for (int i = tid; i < BATCH; i += 1024) {
        int p = atomicAdd(&scur[t[i]], 1);
        g_ridx[p] = i;
        g_pos[i] = p;
    }
}

// ========================= preprocessing =========================
__global__ void xsplit_kernel(const float* __restrict__ x, __nv_bfloat16* __restrict__ hi,
                              __nv_bfloat16* __restrict__ lo, int n) {
    int i = blockIdx.x * blockDim.x + threadIdx.x;
    if (i < n) {
        float v = x[i];
        __nv_bfloat16 h = __float2bfloat16(v);
        hi[i] = h;
        lo[i] = __float2bfloat16(v - __bfloat162float(h));
    }
}
struct WEnt { const float* p; unsigned long long off; int kd, n; };
struct WTab { WEnt e[15]; };
__global__ void wsplit_all(WTab tab, __nv_bfloat16* __restrict__ hi, __nv_bfloat16* __restrict__ lo) {
    WEnt E = tab.e[blockIdx.z];
    int n0 = blockIdx.x * 32, k0 = blockIdx.y * 32;
    if (n0 >= E.n || k0 >= E.kd) return;
    __shared__ float tile[32][33];
    int tx = threadIdx.x, ty = threadIdx.y;
    for (int i = ty; i < 32; i += 8)
        tile[i][tx] = E.p[(size_t)(k0 + i) * E.n + n0 + tx];
    __syncthreads();
    __nv_bfloat16* H = hi + E.off;
    __nv_bfloat16* L = lo + E.off;
    for (int i = ty; i < 32; i += 8) {
        float v = tile[tx][i];
        size_t o = (size_t)(n0 + i) * E.kd + k0 + tx;
        __nv_bfloat16 h = __float2bfloat16(v);
        H[o] = h;
        L[o] = __float2bfloat16(v - __bfloat162float(h));
    }
}

// ========================= TMA-fed 3xBF16 mma.sync GEMM core =========================
// CTA tile 256x128, K-chunk 32 (64B rows, SW64), 512 threads = 16 warps, warp tile 64x32.
// PERSISTENT: each CTA loops tiles; 4-stage chunk stream flows across tile boundaries.
#define S_AH 0
#define S_AL 16384
#define S_BH 32768
#define S_BL 40960
#define STAGE_SZ 49152
#define CHUNK_BYTES 49152u
#define NSTAGE 4
#define SMEM_REQ 198688

__device__ __forceinline__ void compute_chunk(uint32_t st, int warp_m, int warp_n, int lane,
                                              float acc[4][4][4])
{
    const int lrow = lane & 7;
    const int lmat = lane >> 3;
#pragma unroll
    for (int ks = 0; ks < 2; ks++) {
        uint32_t bh[8], bl[8];
#pragma unroll
        for (int p = 0; p < 2; p++) {
            int ntile = p * 2 + (lmat >> 1);
            int half = lmat & 1;
            uint32_t off = (uint32_t)((warp_n * 32 + ntile * 8 + lrow) * 64 + (ks * 16 + half * 8) * 2);
            uint32_t a = swz64(off);
            ldmx4(bh[p * 4 + 0], bh[p * 4 + 1], bh[p * 4 + 2], bh[p * 4 + 3], st + S_BH + a);
            ldmx4(bl[p * 4 + 0], bl[p * 4 + 1], bl[p * 4 + 2], bl[p * 4 + 3], st + S_BL + a);
        }
#pragma unroll
        for (int mt = 0; mt < 4; mt++) {
            uint32_t ah[4], al[4];
            uint32_t off = (uint32_t)((warp_m * 64 + mt * 16 + (lmat & 1) * 8 + lrow) * 64
                                      + (ks * 16 + (lmat >> 1) * 8) * 2);
            uint32_t a = swz64(off);
            ldmx4(ah[0], ah[1], ah[2], ah[3], st + S_AH + a);
            ldmx4(al[0], al[1], al[2], al[3], st + S_AL + a);
#pragma unroll
            for (int nt = 0; nt < 4; nt++) {
                mma16816(acc[mt][nt], ah, bh[nt * 2], bh[nt * 2 + 1]);
                mma16816(acc[mt][nt], ah, bl[nt * 2], bl[nt * 2 + 1]);
                mma16816(acc[mt][nt], al, bh[nt * 2], bh[nt * 2 + 1]);
            }
        }
    }
}

#define PERS_INIT()                                                              \
    if (tid == 0) {                                                              \
        for (int s = 0; s < NSTAGE; s++) {                                       \
            MBARRIER_INIT(mbar + s * 8, 1);                                      \
            MBARRIER_INIT(mbar + 32 + s * 8, 16);                                \
        }                                                                        \
    }                                                                            \
    __syncthreads();

#define PERS_ISSUE(PT, PK, STAGE)                                                \
    {                                                                            \
        uint32_t st_ = ab + (STAGE) * STAGE_SZ;                                  \
        uint32_t mb_ = mbar + (STAGE) * 8;                                       \
        int pbm_ = ((PT) / ntN) * 256, pbn_ = ((PT) % ntN) * 128;                \
        MBARRIER_EXPECT_TX(mb_, CHUNK_BYTES);                                    \
        tma2d(st_ + S_AH, &tAh, (PK) * 32, pbm_, mb_);                           \
        tma2d(st_ + S_AL, &tAl, (PK) * 32, pbm_, mb_);                           \
        tma2d(st_ + S_BH, &tBh, (PK) * 32, pbn_, mb_);                           \
        tma2d(st_ + S_BL, &tBl, (PK) * 32, pbn_, mb_);                           \
    }

// ---- persistent GEMM: C = elu(A@Wt^T + bias), output f32 or hi/lo bf16 ----
template<bool OUT_F32>
__global__ void __launch_bounds__(512, 1)
gemmT(const __grid_constant__ CUtensorMap tAh, const __grid_constant__ CUtensorMap tAl,
      const __grid_constant__ CUtensorMap tBh, const __grid_constant__ CUtensorMap tBl,
      const float* __restrict__ bias, int N, int Kd,
      float* __restrict__ outF, __nv_bfloat16* __restrict__ outHi, __nv_bfloat16* __restrict__ outLo,
      int ntN, int nTiles)
{
    extern __shared__ char smraw[];
    uint32_t sb = smem_u32(smraw);
    uint32_t ab = (sb + 1023u) & ~1023u;
    const uint32_t mbar = ab + NSTAGE * STAGE_SZ;
    const int tid = threadIdx.x;
    const int wid = tid >> 5;
    const int lane = tid & 31;
    const int warp_m = wid & 3;
    const int warp_n = wid >> 2;
    const int nc = Kd >> 5;

    if (blockIdx.x >= (unsigned)nTiles) return;
    PERS_INIT()

    int tiles_mine = 0;
    for (int t = blockIdx.x; t < nTiles; t += gridDim.x) tiles_mine++;
    const long total = (long)tiles_mine * nc;

    int p_t = blockIdx.x, p_k = 0;
    if (tid == 0) {
        long lim = total < 3 ? total : 3;
        for (long i = 0; i < lim; i++) {
            PERS_ISSUE(p_t, p_k, (int)i)
            if (++p_k == nc) { p_k = 0; p_t += gridDim.x; }
        }
    }

    long g = 0;
    for (int t = blockIdx.x; t < nTiles; t += gridDim.x) {
        const int bm = (t / ntN) * 256, bn = (t % ntN) * 128;
        float acc[4][4][4];
#pragma unroll
        for (int i = 0; i < 4; i++)
#pragma unroll
            for (int j = 0; j < 4; j++)
#pragma unroll
                for (int q = 0; q < 4; q++) acc[i][j][q] = 0.f;

        for (int ch = 0; ch < nc; ch++, g++) {
            int s = (int)(g & 3);
            MBARRIER_WAIT_PARITY(mbar + s * 8, (int)((g >> 2) & 1));
            compute_chunk(ab + s * STAGE_SZ, warp_m, warp_n, lane, acc);
            if (lane == 0) MBARRIER_ARRIVE(mbar + 32 + s * 8);
            if (tid == 0) {
                long j = g + 3;
                if (j < total) {
                    int s3 = (int)(j & 3);
                    if (j >= 4) MBARRIER_WAIT_PARITY(mbar + 32 + s3 * 8, (int)(((j >> 2) - 1) & 1));
                    PERS_ISSUE(p_t, p_k, s3)
                    if (++p_k == nc) { p_k = 0; p_t += gridDim.x; }
                }
            }
        }

        const int tgm = lane >> 2;
        const int tgn = (lane & 3) * 2;
#pragma unroll
        for (int mt = 0; mt < 4; mt++) {
#pragma unroll
            for (int dh = 0; dh < 2; dh++) {
                int m = bm + warp_m * 64 + mt * 16 + tgm + dh * 8;
#pragma unroll
                for (int nt = 0; nt < 4; nt++) {
                    int n = bn + warp_n * 32 + nt * 8 + tgn;
                    float v0 = acc[mt][nt][dh * 2 + 0];
                    float v1 = acc[mt][nt][dh * 2 + 1];
                    float2 bb = *(const float2*)(bias + n);
                    v0 = elu_f(v0 + bb.x); v1 = elu_f(v1 + bb.y);
                    if (OUT_F32) {
                        *(float2*)(outF + (size_t)m * N + n) = make_float2(v0, v1);
                    } else {
                        __nv_bfloat16 h0 = __float2bfloat16(v0);
                        __nv_bfloat16 h1 = __float2bfloat16(v1);
                        __nv_bfloat162 hp; hp.x = h0; hp.y = h1;
                        __nv_bfloat162 lp;
                        lp.x = __float2bfloat16(v0 - __bfloat162float(h0));
                        lp.y = __float2bfloat16(v1 - __bfloat162float(h1));
                        *(__nv_bfloat162*)(outHi + (size_t)m * N + n) = hp;
                        *(__nv_bfloat162*)(outLo + (size_t)m * N + n) = lp;
                    }
                }
            }
        }
    }
}

// ---- persistent batched layer-1 GEMM: N=3328 = [y|d|z|t] ----
struct L1Out {
    __nv_bfloat16* hi[4];
    __nv_bfloat16* lo[4];
    const float* bias[4];
};
__global__ void __launch_bounds__(512, 1)
gemmL1(const __grid_constant__ CUtensorMap tAh, const __grid_constant__ CUtensorMap tAl,
       const __grid_constant__ CUtensorMap tBh, const __grid_constant__ CUtensorMap tBl,
       L1Out O, const float* __restrict__ yv, const float* __restrict__ dv,
       const float* __restrict__ wyd, const int* __restrict__ posmap)
{
    extern __shared__ char smraw[];
    uint32_t sb = smem_u32(smraw);
    uint32_t ab = (sb + 1023u) & ~1023u;
    const uint32_t mbar = ab + NSTAGE * STAGE_SZ;
    const int tid = threadIdx.x;
    const int wid = tid >> 5;
    const int lane = tid & 31;
    const int warp_m = wid & 3;
    const int warp_n = wid >> 2;
    const int nc = 32;
    const int ntN = 26;
    const int nTiles = 26 * 64;

    PERS_INIT()

    int tiles_mine = 0;
    for (int t = blockIdx.x; t < nTiles; t += gridDim.x) tiles_mine++;
    const long total = (long)tiles_mine * nc;

    int p_t = blockIdx.x, p_k = 0;
    if (tid == 0) {
        for (long i = 0; i < 3; i++) {
            PERS_ISSUE(p_t, p_k, (int)i)
            if (++p_k == nc) { p_k = 0; p_t += gridDim.x; }
        }
    }

    long g = 0;
    for (int t = blockIdx.x; t < nTiles; t += gridDim.x) {
        const int bm = (t / ntN) * 256;
        const int bnT = (t % ntN) * 128;
        const int seg = bnT >> 10;            // 0=y 1=d 2=z 3=t
        const int bn = bnT & 1023;
        float acc[4][4][4];
#pragma unroll
        for (int i = 0; i < 4; i++)
#pragma unroll
            for (int j = 0; j < 4; j++)
#pragma unroll
                for (int q = 0; q < 4; q++) acc[i][j][q] = 0.f;

        for (int ch = 0; ch < nc; ch++, g++) {
            int s = (int)(g & 3);
            MBARRIER_WAIT_PARITY(mbar + s * 8, (int)((g >> 2) & 1));
            compute_chunk(ab + s * STAGE_SZ, warp_m, warp_n, lane, acc);
            if (lane == 0) MBARRIER_ARRIVE(mbar + 32 + s * 8);
            if (tid == 0) {
                long j = g + 3;
                if (j < total) {
                    int s3 = (int)(j & 3);
                    if (j >= 4) MBARRIER_WAIT_PARITY(mbar + 32 + s3 * 8, (int)(((j >> 2) - 1) & 1));
                    PERS_ISSUE(p_t, p_k, s3)
                    if (++p_k == nc) { p_k = 0; p_t += gridDim.x; }
                }
            }
        }

        __nv_bfloat16* oh = O.hi[seg];
        __nv_bfloat16* ol = O.lo[seg];
        const float* bias = O.bias[seg];
        const bool isZ = (seg == 2);
        const int segN = (seg == 3) ? 256 : 1024;
        const int tgm = lane >> 2;
        const int tgn = (lane & 3) * 2;
#pragma unroll
        for (int mt = 0; mt < 4; mt++) {
#pragma unroll
            for (int dh = 0; dh < 2; dh++) {
                int m = bm + warp_m * 64 + mt * 16 + tgm + dh * 8;
                float ya = 0.f, da = 0.f;
                int mo = m;
                if (isZ) { ya = __ldg(yv + m); da = __ldg(dv + m); mo = __ldg(posmap + m); }
#pragma unroll
                for (int nt = 0; nt < 4; nt++) {
                    int n = bn + warp_n * 32 + nt * 8 + tgn;
                    float v0 = acc[mt][nt][dh * 2 + 0];
                    float v1 = acc[mt][nt][dh * 2 + 1];
                    float2 bb = *(const float2*)(bias + n);
                    v0 += bb.x; v1 += bb.y;
                    if (isZ) {
                        float2 w0 = *(const float2*)(wyd + n);
                        float2 w1 = *(const float2*)(wyd + 1024 + n);
                        v0 += ya * w0.x + da * w1.x;
                        v1 += ya * w0.y + da * w1.y;
                    }
                    v0 = elu_f(v0); v1 = elu_f(v1);
                    __nv_bfloat16 h0 = __float2bfloat16(v0);
                    __nv_bfloat16 h1 = __float2bfloat16(v1);
                    __nv_bfloat162 hp; hp.x = h0; hp.y = h1;
                    __nv_bfloat162 lp;
                    lp.x = __float2bfloat16(v0 - __bfloat162float(h0));
                    lp.y = __float2bfloat16(v1 - __bfloat162float(h1));
                    *(__nv_bfloat162*)(oh + (size_t)mo * segN + n) = hp;
                    *(__nv_bfloat162*)(ol + (size_t)mo * segN + n) = lp;
                }
            }
        }
    }
}

// ---- persistent merged layer-2 GEMM: 1536 tiles = 3 x 512 (y2, d2, z2) ----
__global__ void __launch_bounds__(512, 1)
gemmL2(const __grid_constant__ CUtensorMap tA0h, const __grid_constant__ CUtensorMap tA0l,
       const __grid_constant__ CUtensorMap tA1h, const __grid_constant__ CUtensorMap tA1l,
       const __grid_constant__ CUtensorMap tA2h, const __grid_constant__ CUtensorMap tA2l,
       const __grid_constant__ CUtensorMap tB0h, const __grid_constant__ CUtensorMap tB0l,
       const __grid_constant__ CUtensorMap tB1h, const __grid_constant__ CUtensorMap tB1l,
       const __grid_constant__ CUtensorMap tB2h, const __grid_constant__ CUtensorMap tB2l,
       const float* __restrict__ b0, const float* __restrict__ b1, const float* __restrict__ b2,
       float* __restrict__ fy, float* __restrict__ fd,
       __nv_bfloat16* __restrict__ z2hi, __nv_bfloat16* __restrict__ z2lo)
{
    extern __shared__ char smraw[];
    uint32_t sb = smem_u32(smraw);
    uint32_t ab = (sb + 1023u) & ~1023u;
    const uint32_t mbar = ab + NSTAGE * STAGE_SZ;
    const int tid = threadIdx.x;
    const int wid = tid >> 5;
    const int lane = tid & 31;
    const int warp_m = wid & 3;
    const int warp_n = wid >> 2;
    const int nc = 32;
    const int nTiles = 1536;

    const CUtensorMap* Ah[3] = { &tA0h, &tA1h, &tA2h };
    const CUtensorMap* Al[3] = { &tA0l, &tA1l, &tA2l };
    const CUtensorMap* Bh[3] = { &tB0h, &tB1h, &tB2h };
    const CUtensorMap* Bl[3] = { &tB0l, &tB1l, &tB2l };
    const float* biases[3] = { b0, b1, b2 };

    PERS_INIT()

    int tiles_mine = 0;
    for (int t = blockIdx.x; t < nTiles; t += gridDim.x) tiles_mine++;
    const long total = (long)tiles_mine * nc;

    auto issue = [&](int pt, int pk, int stage) {
        int seg_ = pt >> 9, ts_ = pt & 511;
        int bm_ = (ts_ >> 3) * 256, bn_ = (ts_ & 7) * 128;
        uint32_t st_ = ab + stage * STAGE_SZ;
        uint32_t mb_ = mbar + stage * 8;
        MBARRIER_EXPECT_TX(mb_, CHUNK_BYTES);
        tma2d(st_ + S_AH, Ah[seg_], pk * 32, bm_, mb_);
        tma2d(st_ + S_AL, Al[seg_], pk * 32, bm_, mb_);
        tma2d(st_ + S_BH, Bh[seg_], pk * 32, bn_, mb_);
        tma2d(st_ + S_BL, Bl[seg_], pk * 32, bn_, mb_);
    };

    int p_t = blockIdx.x, p_k = 0;
    if (tid == 0) {
        for (long i = 0; i < 3; i++) {
            issue(p_t, p_k, (int)i);
            if (++p_k == nc) { p_k = 0; p_t += gridDim.x; }
        }
    }

    long g = 0;
    for (int t = blockIdx.x; t < nTiles; t += gridDim.x) {
        const int seg = t >> 9, ts = t & 511;
        const int bm = (ts >> 3) * 256, bn = (ts & 7) * 128;
        float acc[4][4][4];
#pragma unroll
        for (int i = 0; i < 4; i++)
#pragma unroll
            for (int j = 0; j < 4; j++)
#pragma unroll
                for (int q = 0; q < 4; q++) acc[i][j][q] = 0.f;

        for (int ch = 0; ch < nc; ch++, g++) {
            int s = (int)(g & 3);
            MBARRIER_WAIT_PARITY(mbar + s * 8, (int)((g >> 2) & 1));
            compute_chunk(ab + s * STAGE_SZ, warp_m, warp_n, lane, acc);
            if (lane == 0) MBARRIER_ARRIVE(mbar + 32 + s * 8);
            if (tid == 0) {
                long j = g + 3;
                if (j < total) {
                    int s3 = (int)(j & 3);
                    if (j >= 4) MBARRIER_WAIT_PARITY(mbar + 32 + s3 * 8, (int)(((j >> 2) - 1) & 1));
                    issue(p_t, p_k, s3);
                    if (++p_k == nc) { p_k = 0; p_t += gridDim.x; }
                }
            }
        }

        const float* bias = biases[seg];
        const int tgm = lane >> 2;
        const int tgn = (lane & 3) * 2;
#pragma unroll
        for (int mt = 0; mt < 4; mt++) {
#pragma unroll
            for (int dh = 0; dh < 2; dh++) {
                int m = bm + warp_m * 64 + mt * 16 + tgm + dh * 8;
#pragma unroll
                for (int nt = 0; nt < 4; nt++) {
                    int n = bn + warp_n * 32 + nt * 8 + tgn;
                    float v0 = acc[mt][nt][dh * 2 + 0];
                    float v1 = acc[mt][nt][dh * 2 + 1];
                    float2 bb = *(const float2*)(bias + n);
                    v0 = elu_f(v0 + bb.x); v1 = elu_f(v1 + bb.y);
                    if (seg < 2) {
                        float* o = seg ? fd : fy;
                        *(float2*)(o + (size_t)m * 1024 + n) = make_float2(v0, v1);
                    } else {
                        __nv_bfloat16 h0 = __float2bfloat16(v0);
                        __nv_bfloat16 h1 = __float2bfloat16(v1);
                        __nv_bfloat162 hp; hp.x = h0; hp.y = h1;
                        __nv_bfloat162 lp;
                        lp.x = __float2bfloat16(v0 - __bfloat162float(h0));
                        lp.y = __float2bfloat16(v1 - __bfloat162float(h1));
                        *(__nv_bfloat162*)(z2hi + (size_t)m * 1024 + n) = hp;
                        *(__nv_bfloat162*)(z2lo + (size_t)m * 1024 + n) = lp;
                    }
                }
            }
        }
    }
}

// ---- z head: grouped GEMM over gathered rows ----
__global__ void __launch_bounds__(512, 1)
zheadT(const __grid_constant__ CUtensorMap tAh, const __grid_constant__ CUtensorMap tAl,
       const __grid_constant__ CUtensorMap tBh, const __grid_constant__ CUtensorMap tBl,
       const float* __restrict__ zhb, float* __restrict__ out)
{
    const int grp = blockIdx.z;
    const int cnt = g_cnt[grp];
    const int m0 = blockIdx.y * 256;
    if (m0 >= cnt) return;
    const int base = g_off[grp];
    const int bn = blockIdx.x * 128;
    const int brow = grp * 512 + bn;
    const int arow = base + m0;

    extern __shared__ char smraw[];
    uint32_t sb = smem_u32(smraw);
    uint32_t ab = (sb + 1023u) & ~1023u;
    const uint32_t mbar = ab + NSTAGE * STAGE_SZ;
    const int tid = threadIdx.x;
    const int wid = tid >> 5;
    const int lane = tid & 31;
    const int warp_m = wid & 3;
    const int warp_n = wid >> 2;

    PERS_INIT()

    if (tid == 0) {
        for (int p = 0; p < 3; p++) {
            uint32_t st = ab + p * STAGE_SZ;
            uint32_t mb = mbar + p * 8;
            MBARRIER_EXPECT_TX(mb, CHUNK_BYTES);
            tma2d(st + S_AH, &tAh, p * 32, arow, mb);
            tma2d(st + S_AL, &tAl, p * 32, arow, mb);
            tma2d(st + S_BH, &tBh, p * 32, brow, mb);
            tma2d(st + S_BL, &tBl, p * 32, brow, mb);
        }
    }

    float acc[4][4][4];
#pragma unroll
    for (int i = 0; i < 4; i++)
#pragma unroll
        for (int j = 0; j < 4; j++)
#pragma unroll
            for (int q = 0; q < 4; q++) acc[i][j][q] = 0.f;

    for (int ch = 0; ch < 32; ch++) {
        int s = ch & 3;
        MBARRIER_WAIT_PARITY(mbar + s * 8, (ch >> 2) & 1);
        compute_chunk(ab + s * STAGE_SZ, warp_m, warp_n, lane, acc);
        if (lane == 0) MBARRIER_ARRIVE(mbar + 32 + s * 8);
        if (tid == 0 && ch + 3 < 32) {
            int s3 = (ch + 3) & 3;
            if (ch >= 1) MBARRIER_WAIT_PARITY(mbar + 32 + s3 * 8, (((ch + 3) >> 2) - 1) & 1);
            uint32_t st = ab + s3 * STAGE_SZ;
            uint32_t mb = mbar + s3 * 8;
            int k0 = (ch + 3) * 32;
            MBARRIER_EXPECT_TX(mb, CHUNK_BYTES);
            tma2d(st + S_AH, &tAh, k0, arow, mb);
            tma2d(st + S_AL, &tAl, k0, arow, mb);
            tma2d(st + S_BH, &tBh, k0, brow, mb);
            tma2d(st + S_BL, &tBl, k0, brow, mb);
        }
    }

    const int tgm = lane >> 2;
    const int tgn = (lane & 3) * 2;
#pragma unroll
    for (int mt = 0; mt < 4; mt++) {
#pragma unroll
        for (int dh = 0; dh < 2; dh++) {
            int mloc = warp_m * 64 + mt * 16 + tgm + dh * 8;
            int gi = m0 + mloc;
            if (gi >= cnt) continue;
            int rg = g_ridx[base + gi];
            float* op = out + (size_t)rg * OUTC + 11;
#pragma unroll
            for (int nt = 0; nt < 4; nt++) {
                int n = bn + warp_n * 32 + nt * 8 + tgn;
                float v0 = acc[mt][nt][dh * 2 + 0] + __ldg(zhb + grp * 512 + n);
                float v1 = acc[mt][nt][dh * 2 + 1] + __ldg(zhb + grp * 512 + n + 1);
                if (n < 256) {
                    v0 = fminf(fmaxf(v0, -100.f), 100.f);
                    v1 = fminf(fmaxf(v1, -100.f), 100.f);
                } else {
                    v0 = fminf(softplus_f(v0) + 0.001f, 100.f);
                    v1 = fminf(softplus_f(v1) + 0.001f, 100.f);
                }
                op[n] = v0;
                op[n + 1] = v1;
            }
        }
    }
}

// ========================= small head kernels (fp32) =========================
__global__ void thead_kernel(const float* __restrict__ hid, const float* __restrict__ tw2,
                             const float* __restrict__ tb2, float* __restrict__ out)
{
    int w = (blockIdx.x * blockDim.x + threadIdx.x) >> 5;
    int lane = threadIdx.x & 31;
    if (w >= BATCH) return;
    const float* hr = hid + (size_t)w * 256;
    float acc[7] = {0.f, 0.f, 0.f, 0.f, 0.f, 0.f, 0.f};
    for (int k = lane; k < 256; k += 32) {
        float h = hr[k];
        const float* wr = tw2 + k * 7;
#pragma unroll
        for (int j = 0; j < 7; j++) acc[j] = fmaf(h, wr[j], acc[j]);
    }
#pragma unroll
    for (int j = 0; j < 7; j++)
        for (int o = 16; o > 0; o >>= 1) acc[j] += __shfl_xor_sync(0xffffffffu, acc[j], o);
    if (lane == 0) {
#pragma unroll
        for (int j = 0; j < 7; j++) {
            float v = elu_f(acc[j] + tb2[j]);
            out[(size_t)w * OUTC + j] = fminf(fmaxf(v, -10.f), 10.f);
        }
    }
}
__global__ void head2_kernel(const float* __restrict__ hid, const int* __restrict__ t,
                             const float* __restrict__ hW, const float* __restrict__ hb,
                             float* __restrict__ out, int col0)
{
    int w = (blockIdx.x * blockDim.x + threadIdx.x) >> 5;
    int lane = threadIdx.x & 31;
    if (w >= BATCH) return;
    int tt = t[w];
    const float*  hr = hid + (size_t)w * 1024;
    const float2* wp = (const float2*)(hW + (size_t)tt * 2048);
    float a0 = 0.f, a1 = 0.f;
    for (int k = lane; k < 1024; k += 32) {
        float h = hr[k];
        float2 ww = wp[k];
        a0 = fmaf(h, ww.x, a0);
        a1 = fmaf(h, ww.y, a1);
    }
    for (int o = 16; o > 0; o >>= 1) {
        a0 += __shfl_xor_sync(0xffffffffu, a0, o);
        a1 += __shfl_xor_sync(0xffffffffu, a1, o);
    }
    if (lane == 0) {
        float loc = fminf(fmaxf(a0 + hb[tt * 2 + 0], -1e6f), 1e6f);
        float sc  = fminf(softplus_f(a1 + hb[tt * 2 + 1]) + 1e-3f, 1e6f);
        out[(size_t)w * OUTC + col0]     = loc;
        out[(size_t)w * OUTC + col0 + 1] = sc;
    }
}

// ========================= host-side tensormap builder =========================
typedef CUresult (*PFN_tmap)(CUtensorMap*, CUtensorMapDataType, cuuint32_t, void*,
                             const cuuint64_t*, const cuuint64_t*, const cuuint32_t*,
                             const cuuint32_t*, CUtensorMapInterleave, CUtensorMapSwizzle,
                             CUtensorMapL2promotion, CUtensorMapFloatOOBfill);
static PFN_tmap tmap_fn() {
    static PFN_tmap fn = nullptr;
    if (!fn) {
        cudaDriverEntryPointQueryResult qr;
        cudaGetDriverEntryPointByVersion("cuTensorMapEncodeTiled", (void**)&fn, 12000,
                                         cudaEnableDefault, &qr);
    }
    return fn;
}
static void make_map(CUtensorMap* m, const __nv_bfloat16* base, unsigned long long inner,
                     unsigned long long outer, unsigned box_in, unsigned box_out) {
    cuuint64_t dims[2] = { inner, outer };
    cuuint64_t strides[1] = { inner * 2 };
    cuuint32_t box[2] = { box_in, box_out };
    cuuint32_t es[2] = { 1, 1 };
    tmap_fn()(m, CU_TENSOR_MAP_DATA_TYPE_BFLOAT16, 2, (void*)base, dims, strides, box, es,
              CU_TENSOR_MAP_INTERLEAVE_NONE, CU_TENSOR_MAP_SWIZZLE_64B,
              CU_TENSOR_MAP_L2_PROMOTION_L2_128B, CU_TENSOR_MAP_FLOAT_OOB_FILL_NONE);
}

// ========================= launch =========================
extern "C" void kernel_launch(void* const* d_in, const int* in_sizes, int n_in,
                              void* d_out, int out_size)
{
    const float* x   = (const float*)d_in[0];
    const int*   t   = (const int*)  d_in[1];
    const float* yv  = (const float*)d_in[2];
    const float* dv  = (const float*)d_in[3];
    const float* tw0 = (const float*)d_in[4];
    const float* tb0 = (const float*)d_in[5];
    const float* tw1 = (const float*)d_in[6];
    const float* tb1 = (const float*)d_in[7];
    const float* tw2 = (const float*)d_in[8];
    const float* tb2 = (const float*)d_in[9];
    const float* yw0 = (const float*)d_in[10];
    const float* yb0 = (const float*)d_in[11];
    const float* yw1 = (const float*)d_in[12];
    const float* yb1 = (const float*)d_in[13];
    const float* yhW = (const float*)d_in[14];
    const float* yhb = (const float*)d_in[15];
    const float* dw0 = (const float*)d_in[16];
    const float* db0 = (const float*)d_in[17];
    const float* dw1 = (const float*)d_in[18];
    const float* db1 = (const float*)d_in[19];
    const float* dhW = (const float*)d_in[20];
    const float* dhb = (const float*)d_in[21];
    const float* zw0 = (const float*)d_in[22];
    const float* zb0 = (const float*)d_in[23];
    const float* zw1 = (const float*)d_in[24];
    const float* zb1 = (const float*)d_in[25];
    const float* zhW = (const float*)d_in[26];
    const float* zhb = (const float*)d_in[27];
    float* out = (float*)d_out;

    __nv_bfloat16 *xhi, *xlo, *y1hi, *y1lo, *d1hi, *d1lo, *z1hi, *z1lo, *z2hi, *z2lo, *t1hi, *t1lo, *whi, *wlo;
    float *fy, *fd, *ft;
    int *posmap;
    cudaGetSymbolAddress((void**)&xhi, g_xhi);
    cudaGetSymbolAddress((void**)&xlo, g_xlo);
    cudaGetSymbolAddress((void**)&y1hi, g_y1hi);
    cudaGetSymbolAddress((void**)&y1lo, g_y1lo);
    cudaGetSymbolAddress((void**)&d1hi, g_d1hi);
    cudaGetSymbolAddress((void**)&d1lo, g_d1lo);
    cudaGetSymbolAddress((void**)&z1hi, g_z1hi);
    cudaGetSymbolAddress((void**)&z1lo, g_z1lo);
    cudaGetSymbolAddress((void**)&z2hi, g_z2hi);
    cudaGetSymbolAddress((void**)&z2lo, g_z2lo);
    cudaGetSymbolAddress((void**)&t1hi, g_t1hi);
    cudaGetSymbolAddress((void**)&t1lo, g_t1lo);
    cudaGetSymbolAddress((void**)&whi, g_whi);
    cudaGetSymbolAddress((void**)&wlo, g_wlo);
    cudaGetSymbolAddress((void**)&fy, g_fy);
    cudaGetSymbolAddress((void**)&fd, g_fd);
    cudaGetSymbolAddress((void**)&ft, g_ft);
    cudaGetSymbolAddress((void**)&posmap, g_pos);

    static cudaStream_t s1, s2, s3;
    static cudaEvent_t eL1, eL2, eJ1, eJ2, eJ3;
    static bool init = false;
    if (!init) {
        cudaStreamCreateWithFlags(&s1, cudaStreamNonBlocking);
        cudaStreamCreateWithFlags(&s2, cudaStreamNonBlocking);
        cudaStreamCreateWithFlags(&s3, cudaStreamNonBlocking);
        cudaEventCreateWithFlags(&eL1, cudaEventDisableTiming);
        cudaEventCreateWithFlags(&eL2, cudaEventDisableTiming);
        cudaEventCreateWithFlags(&eJ1, cudaEventDisableTiming);
        cudaEventCreateWithFlags(&eJ2, cudaEventDisableTiming);
        cudaEventCreateWithFlags(&eJ3, cudaEventDisableTiming);
        cudaFuncSetAttribute((const void*)gemmT<true>,  cudaFuncAttributeMaxDynamicSharedMemorySize, SMEM_REQ);
        cudaFuncSetAttribute((const void*)gemmT<false>, cudaFuncAttributeMaxDynamicSharedMemorySize, SMEM_REQ);
        cudaFuncSetAttribute((const void*)gemmL1,       cudaFuncAttributeMaxDynamicSharedMemorySize, SMEM_REQ);
        cudaFuncSetAttribute((const void*)gemmL2,       cudaFuncAttributeMaxDynamicSharedMemorySize, SMEM_REQ);
        cudaFuncSetAttribute((const void*)zheadT,       cudaFuncAttributeMaxDynamicSharedMemorySize, SMEM_REQ);
        init = true;
    }

    static CUtensorMap M[24];
    make_map(&M[0],  xhi,  1024, BATCH, 32, 256);
    make_map(&M[1],  xlo,  1024, BATCH, 32, 256);
    make_map(&M[2],  y1hi, 1024, BATCH, 32, 256);
    make_map(&M[3],  y1lo, 1024, BATCH, 32, 256);
    make_map(&M[4],  d1hi, 1024, BATCH, 32, 256);
    make_map(&M[5],  d1lo, 1024, BATCH, 32, 256);
    make_map(&M[6],  z1hi, 1024, BATCH, 32, 256);
    make_map(&M[7],  z1lo, 1024, BATCH, 32, 256);
    make_map(&M[8],  z2hi, 1024, BATCH, 32, 256);
    make_map(&M[9],  z2lo, 1024, BATCH, 32, 256);
    make_map(&M[10], t1hi, 256,  BATCH, 32, 256);
    make_map(&M[11], t1lo, 256,  BATCH, 32, 256);
    make_map(&M[12], whi + OFF_TW1, 256,  256,  32, 128);
    make_map(&M[13], wlo + OFF_TW1, 256,  256,  32, 128);
    make_map(&M[14], whi + OFF_L1,  1024, 3328, 32, 128);
    make_map(&M[15], wlo + OFF_L1,  1024, 3328, 32, 128);
    make_map(&M[16], whi + OFF_YW1, 1024, 1024, 32, 128);
    make_map(&M[17], wlo + OFF_YW1, 1024, 1024, 32, 128);
    make_map(&M[18], whi + OFF_DW1, 1024, 1024, 32, 128);
    make_map(&M[19], wlo + OFF_DW1, 1024, 1024, 32, 128);
    make_map(&M[20], whi + OFF_ZW1, 1024, 1024, 32, 128);
    make_map(&M[21], wlo + OFF_ZW1, 1024, 1024, 32, 128);
    make_map(&M[22], whi + OFF_ZHW, 1024, 3584, 32, 128);
    make_map(&M[23], wlo + OFF_ZHW, 1024, 3584, 32, 128);

    bucket_all<<<1, 1024>>>(t);
    xsplit_kernel<<<(BATCH * 1024 + 255) / 256, 256>>>(x, xhi, xlo, BATCH * 1024);
    WTab tab;
    tab.e[0]  = { tw1,            OFF_TW1,               256,  256 };
    tab.e[1]  = { yw0,            OFF_L1,                1024, 1024 };
    tab.e[2]  = { dw0,            OFF_L1 + 1048576ull,   1024, 1024 };
    tab.e[3]  = { zw0 + 2 * 1024, OFF_L1 + 2097152ull,   1024, 1024 };
    tab.e[4]  = { tw0,            OFF_L1 + 3145728ull,   1024, 256 };
    tab.e[5]  = { yw1,            OFF_YW1,               1024, 1024 };
    tab.e[6]  = { dw1,            OFF_DW1,               1024, 1024 };
    tab.e[7]  = { zw1,            OFF_ZW1,               1024, 1024 };
    for (int g = 0; g < 7; g++)
        tab.e[8 + g] = { zhW + (size_t)g * 1024 * 512,
                         (unsigned long long)(OFF_ZHW + (size_t)g * 524288), 1024, 512 };
    wsplit_all<<<dim3(32, 32, 15), dim3(32, 8)>>>(tab, whi, wlo);

    // ---- L1 mega (y|d|z|t layer-1) ----
    L1Out O;
    O.hi[0] = y1hi; O.lo[0] = y1lo; O.bias[0] = yb0;
    O.hi[1] = d1hi; O.lo[1] = d1lo; O.bias[1] = db0;
    O.hi[2] = z1hi; O.lo[2] = z1lo; O.bias[2] = zb0;
    O.hi[3] = t1hi; O.lo[3] = t1lo; O.bias[3] = tb0;
    gemmL1<<<148, 512, SMEM_REQ>>>(M[0], M[1], M[14], M[15], O, yv, dv, zw0, posmap);
    cudaEventRecord(eL1, 0);

    // ---- L2 mega (y2 | d2 | z2) ----
    gemmL2<<<148, 512, SMEM_REQ>>>(M[2], M[3], M[4], M[5], M[6], M[7],
                                   M[16], M[17], M[18], M[19], M[20], M[21],
                                   yb1, db1, zb1, fy, fd, z2hi, z2lo);
    cudaEventRecord(eL2, 0);

    const int headBlocks = (BATCH * 32) / 256;

    // ---- tails on streams (small kernels; genuinely concurrent) ----
    cudaStreamWaitEvent(s1, eL1, 0);
    gemmT<true><<<128, 512, SMEM_REQ, s1>>>(M[10], M[11], M[12], M[13], tb1, 256, 256,
                                            ft, nullptr, nullptr, 2, 128);
    thead_kernel<<<headBlocks, 256, 0, s1>>>(ft, tw2, tb2, out);
    cudaEventRecord(eJ1, s1);

    cudaStreamWaitEvent(s2, eL2, 0);
    head2_kernel<<<headBlocks, 256, 0, s2>>>(fy, t, yhW, yhb, out, 7);
    head2_kernel<<<headBlocks, 256, 0, s2>>>(fd, t, dhW, dhb, out, 9);
    cudaEventRecord(eJ2, s2);

    cudaStreamWaitEvent(s3, eL2, 0);
    zheadT<<<dim3(4, 64, 7), 512, SMEM_REQ, s3>>>(M[8], M[9], M[22], M[23], zhb, out);
    cudaEventRecord(eJ3, s3);

    cudaStreamWaitEvent(0, eJ1, 0);
    cudaStreamWaitEvent(0, eJ2, 0);
    cudaStreamWaitEvent(0, eJ3, 0);
}

// round 12
// speedup vs baseline: 1.3049x; 1.3049x over previous
#include <cuda_runtime.h>
#include <cuda.h>
#include <cuda_fp16.h>
#include <cstdint>
#include <math.h>

#define BATCH 16384
#define OUTC  523   // 7 + 4 + 512

// ========================= PTX helpers (baseline sm_90-level, no arch-suffix) =========================
__device__ __forceinline__ uint32_t smem_u32(const void* p) {
    uint32_t a;
    asm("{ .reg .u64 t; cvta.to.shared.u64 t, %1; cvt.u32.u64 %0, t; }" : "=r"(a) : "l"(p));
    return a;
}
__device__ __forceinline__ void ldmx4(uint32_t& r0, uint32_t& r1, uint32_t& r2, uint32_t& r3, uint32_t addr) {
    asm volatile("ldmatrix.sync.aligned.m8n8.x4.shared.b16 {%0,%1,%2,%3}, [%4];"
                 : "=r"(r0), "=r"(r1), "=r"(r2), "=r"(r3) : "r"(addr));
}
__device__ __forceinline__ void mma16816(float* c, const uint32_t* a, uint32_t b0, uint32_t b1) {
    asm volatile("mma.sync.aligned.m16n8k16.row.col.f32.f16.f16.f32 "
                 "{%0,%1,%2,%3}, {%4,%5,%6,%7}, {%8,%9}, {%0,%1,%2,%3};"
                 : "+f"(c[0]), "+f"(c[1]), "+f"(c[2]), "+f"(c[3])
                 : "r"(a[0]), "r"(a[1]), "r"(a[2]), "r"(a[3]), "r"(b0), "r"(b1));
}
// SW64 swizzle: atom = 8 rows x 64B; conflict-free ldmatrix for 64B-row tiles
__device__ __forceinline__ uint32_t swz64(uint32_t off) { return off ^ ((off >> 3) & 0x30); }

__device__ __forceinline__ void tma2d(uint32_t dst, const CUtensorMap* map, int cx, int cy, uint32_t mbar) {
    asm volatile("cp.async.bulk.tensor.2d.shared::cta.global.tile.mbarrier::complete_tx::bytes "
                 "[%0], [%1, {%2, %3}], [%4];"
                 :: "r"(dst), "l"(map), "r"(cx), "r"(cy), "r"(mbar) : "memory");
}
#define MBARRIER_INIT(addr, cnt) \
    asm volatile("mbarrier.init.shared.b64 [%0], %1;" :: "r"((uint32_t)(addr)), "r"((uint32_t)(cnt)) : "memory")
#define MBARRIER_ARRIVE(addr) \
    asm volatile("mbarrier.arrive.shared.b64 _, [%0];" :: "r"((uint32_t)(addr)) : "memory")
#define MBARRIER_EXPECT_TX(addr, bytes) \
    asm volatile("mbarrier.arrive.expect_tx.shared.b64 _, [%0], %1;" \
        :: "r"((uint32_t)(addr)), "r"((uint32_t)(bytes)) : "memory")
#define MBARRIER_WAIT_PARITY(mbar_smem_addr, phase_parity) do { \
    uint32_t _mbar = (uint32_t)(mbar_smem_addr); \
    uint32_t _parity = (uint32_t)(phase_parity); \
    uint32_t _done; \
    asm volatile("{\n\t.reg .pred p;\n\t" \
        "mbarrier.try_wait.parity.acquire.cta.shared::cta.b64 p, [%1], %2;\n\t" \
        "selp.b32 %0, 1, 0, p;\n\t}" : "=r"(_done) : "r"(_mbar), "r"(_parity) : "memory"); \
    if (!_done) { \
        asm volatile("{\n\t.reg .pred P1;\n\t" \
            "WAIT_LOOP_%=:\n\t" \
            "mbarrier.try_wait.parity.acquire.cta.shared::cta.b64 P1, [%0], %1, 0x989680;\n\t" \
            "@P1 bra.uni WAIT_DONE_%=;\n\t" \
            "bra.uni WAIT_LOOP_%=;\n\t" \
            "WAIT_DONE_%=:\n\t}" :: "r"(_mbar), "r"(_parity) : "memory"); \
    } \
} while(0)

// ========================= scratch =========================
__device__ __align__(1024) __half g_xhi[BATCH * 1024];
__device__ __align__(1024) __half g_xlo[BATCH * 1024];
__device__ __align__(1024) __half g_y1hi[BATCH * 1024];
__device__ __align__(1024) __half g_y1lo[BATCH * 1024];
__device__ __align__(1024) __half g_d1hi[BATCH * 1024];
__device__ __align__(1024) __half g_d1lo[BATCH * 1024];
__device__ __align__(1024) __half g_z1hi[BATCH * 1024];   // bucket order
__device__ __align__(1024) __half g_z1lo[BATCH * 1024];
__device__ __align__(1024) __half g_z2hi[BATCH * 1024];   // bucket order
__device__ __align__(1024) __half g_z2lo[BATCH * 1024];
__device__ __align__(1024) __half g_t1hi[BATCH * 256];
__device__ __align__(1024) __half g_t1lo[BATCH * 256];
__device__ float g_fy[BATCH * 1024];
__device__ float g_fd[BATCH * 1024];
__device__ float g_ft[BATCH * 256];
__device__ __align__(1024) __half g_wh[10300000];         // single-fp16 weight pool
__device__ int g_ridx[BATCH];
__device__ int g_pos[BATCH];
__device__ int g_cnt[8];
__device__ int g_off[8];

// weight-pool offsets (elements)
#define OFF_TW1 0             // [256,256]
#define OFF_L1  65536         // [3328,1024]: yw0|dw0|zw0'|tw0
#define OFF_YW1 3473408
#define OFF_DW1 4521984
#define OFF_ZW1 5570560
#define OFF_ZHW 6619136       // [3584,1024]

__device__ __forceinline__ float elu_f(float v) { return v > 0.f ? v : expm1f(v); }
__device__ __forceinline__ float softplus_f(float v) {
    return fmaxf(v, 0.f) + log1pf(expf(-fabsf(v)));
}

// ========================= fused bucketing =========================
__global__ void bucket_all(const int* __restrict__ t) {
    __shared__ int scnt[8];
    __shared__ int scur[8];
    int tid = threadIdx.x;
    if (tid < 8) scnt[tid] = 0;
    __syncthreads();
    for (int i = tid; i < BATCH; i += 1024) atomicAdd(&scnt[t[i]], 1);
    __syncthreads();
    if (tid == 0) {
        int s = 0;
        for (int k = 0; k < 7; k++) { g_cnt[k] = scnt[k]; g_off[k] = s; scur[k] = s; s += scnt[k]; }
    }
    __syncthreads();
    for (int i = tid; i < BATCH; i += 1024) {
        int p = atomicAdd(&scur[t[i]], 1);
        g_ridx[p] = i;
        g_pos[i] = p;
    }
}

// ========================= preprocessing =========================
__global__ void xsplit_kernel(const float* __restrict__ x, __half* __restrict__ hi,
                              __half* __restrict__ lo, int n) {
    int i = blockIdx.x * blockDim.x + threadIdx.x;
    if (i < n) {
        float v = x[i];
        __half h = __float2half(v);
        hi[i] = h;
        lo[i] = __float2half(v - __half2float(h));
    }
}
struct WEnt { const float* p; unsigned long long off; int kd, n; };
struct WTab { WEnt e[15]; };
// transpose + convert to single fp16
__global__ void wconv_all(WTab tab, __half* __restrict__ wp) {
    WEnt E = tab.e[blockIdx.z];
    int n0 = blockIdx.x * 32, k0 = blockIdx.y * 32;
    if (n0 >= E.n || k0 >= E.kd) return;
    __shared__ float tile[32][33];
    int tx = threadIdx.x, ty = threadIdx.y;
    for (int i = ty; i < 32; i += 8)
        tile[i][tx] = E.p[(size_t)(k0 + i) * E.n + n0 + tx];
    __syncthreads();
    __half* W = wp + E.off;
    for (int i = ty; i < 32; i += 8)
        W[(size_t)(n0 + i) * E.kd + k0 + tx] = __float2half(tile[tx][i]);
}

// ========================= TMA-fed 2xFP16 mma.sync GEMM core =========================
// CTA tile 256x128, K-chunk 32 (64B rows, SW64), 512 threads = 16 warps, warp tile 64x32.
// A split hi/lo fp16, W single fp16 -> 2 MMA terms. Persistent tile loop, 4 TMA stages.
#define S_AH 0
#define S_AL 16384
#define S_BW 32768
#define STAGE_SZ 40960
#define CHUNK_BYTES 40960u
#define NSTAGE 4
#define SMEM_REQ 165952

__device__ __forceinline__ void compute_chunk(uint32_t st, int warp_m, int warp_n, int lane,
                                              float acc[4][4][4])
{
    const int lrow = lane & 7;
    const int lmat = lane >> 3;
#pragma unroll
    for (int ks = 0; ks < 2; ks++) {
        uint32_t bw[8];
#pragma unroll
        for (int p = 0; p < 2; p++) {
            int ntile = p * 2 + (lmat >> 1);
            int half_ = lmat & 1;
            uint32_t off = (uint32_t)((warp_n * 32 + ntile * 8 + lrow) * 64 + (ks * 16 + half_ * 8) * 2);
            uint32_t a = swz64(off);
            ldmx4(bw[p * 4 + 0], bw[p * 4 + 1], bw[p * 4 + 2], bw[p * 4 + 3], st + S_BW + a);
        }
#pragma unroll
        for (int mt = 0; mt < 4; mt++) {
            uint32_t ah[4], al[4];
            uint32_t off = (uint32_t)((warp_m * 64 + mt * 16 + (lmat & 1) * 8 + lrow) * 64
                                      + (ks * 16 + (lmat >> 1) * 8) * 2);
            uint32_t a = swz64(off);
            ldmx4(ah[0], ah[1], ah[2], ah[3], st + S_AH + a);
            ldmx4(al[0], al[1], al[2], al[3], st + S_AL + a);
#pragma unroll
            for (int nt = 0; nt < 4; nt++) {
                mma16816(acc[mt][nt], ah, bw[nt * 2], bw[nt * 2 + 1]);
                mma16816(acc[mt][nt], al, bw[nt * 2], bw[nt * 2 + 1]);
            }
        }
    }
}

#define PERS_INIT()                                                              \
    if (tid == 0) {                                                              \
        for (int s = 0; s < NSTAGE; s++) {                                       \
            MBARRIER_INIT(mbar + s * 8, 1);                                      \
            MBARRIER_INIT(mbar + 32 + s * 8, 16);                                \
        }                                                                        \
    }                                                                            \
    __syncthreads();

#define PERS_ISSUE(PT, PK, STAGE)                                                \
    {                                                                            \
        uint32_t st_ = ab + (STAGE) * STAGE_SZ;                                  \
        uint32_t mb_ = mbar + (STAGE) * 8;                                       \
        int pbm_ = ((PT) / ntN) * 256, pbn_ = ((PT) % ntN) * 128;                \
        MBARRIER_EXPECT_TX(mb_, CHUNK_BYTES);                                    \
        tma2d(st_ + S_AH, &tAh, (PK) * 32, pbm_, mb_);                           \
        tma2d(st_ + S_AL, &tAl, (PK) * 32, pbm_, mb_);                           \
        tma2d(st_ + S_BW, &tBw, (PK) * 32, pbn_, mb_);                           \
    }

// ---- persistent GEMM: C = elu(A@Wt^T + bias), output f32 or hi/lo fp16 ----
template<bool OUT_F32>
__global__ void __launch_bounds__(512, 1)
gemmT(const __grid_constant__ CUtensorMap tAh, const __grid_constant__ CUtensorMap tAl,
      const __grid_constant__ CUtensorMap tBw,
      const float* __restrict__ bias, int N, int Kd,
      float* __restrict__ outF, __half* __restrict__ outHi, __half* __restrict__ outLo,
      int ntN, int nTiles)
{
    extern __shared__ char smraw[];
    uint32_t sb = smem_u32(smraw);
    uint32_t ab = (sb + 1023u) & ~1023u;
    const uint32_t mbar = ab + NSTAGE * STAGE_SZ;
    const int tid = threadIdx.x;
    const int wid = tid >> 5;
    const int lane = tid & 31;
    const int warp_m = wid & 3;
    const int warp_n = wid >> 2;
    const int nc = Kd >> 5;

    if (blockIdx.x >= (unsigned)nTiles) return;
    PERS_INIT()

    int tiles_mine = 0;
    for (int t = blockIdx.x; t < nTiles; t += gridDim.x) tiles_mine++;
    const long total = (long)tiles_mine * nc;

    int p_t = blockIdx.x, p_k = 0;
    if (tid == 0) {
        long lim = total < 3 ? total : 3;
        for (long i = 0; i < lim; i++) {
            PERS_ISSUE(p_t, p_k, (int)i)
            if (++p_k == nc) { p_k = 0; p_t += gridDim.x; }
        }
    }

    long g = 0;
    for (int t = blockIdx.x; t < nTiles; t += gridDim.x) {
        const int bm = (t / ntN) * 256, bn = (t % ntN) * 128;
        float acc[4][4][4];
#pragma unroll
        for (int i = 0; i < 4; i++)
#pragma unroll
            for (int j = 0; j < 4; j++)
#pragma unroll
                for (int q = 0; q < 4; q++) acc[i][j][q] = 0.f;

        for (int ch = 0; ch < nc; ch++, g++) {
            int s = (int)(g & 3);
            MBARRIER_WAIT_PARITY(mbar + s * 8, (int)((g >> 2) & 1));
            compute_chunk(ab + s * STAGE_SZ, warp_m, warp_n, lane, acc);
            if (lane == 0) MBARRIER_ARRIVE(mbar + 32 + s * 8);
            if (tid == 0) {
                long j = g + 3;
                if (j < total) {
                    int s3 = (int)(j & 3);
                    if (j >= 4) MBARRIER_WAIT_PARITY(mbar + 32 + s3 * 8, (int)(((j >> 2) - 1) & 1));
                    PERS_ISSUE(p_t, p_k, s3)
                    if (++p_k == nc) { p_k = 0; p_t += gridDim.x; }
                }
            }
        }

        const int tgm = lane >> 2;
        const int tgn = (lane & 3) * 2;
#pragma unroll
        for (int mt = 0; mt < 4; mt++) {
#pragma unroll
            for (int dh = 0; dh < 2; dh++) {
                int m = bm + warp_m * 64 + mt * 16 + tgm + dh * 8;
#pragma unroll
                for (int nt = 0; nt < 4; nt++) {
                    int n = bn + warp_n * 32 + nt * 8 + tgn;
                    float v0 = acc[mt][nt][dh * 2 + 0];
                    float v1 = acc[mt][nt][dh * 2 + 1];
                    float2 bb = *(const float2*)(bias + n);
                    v0 = elu_f(v0 + bb.x); v1 = elu_f(v1 + bb.y);
                    if (OUT_F32) {
                        *(float2*)(outF + (size_t)m * N + n) = make_float2(v0, v1);
                    } else {
                        __half h0 = __float2half(v0);
                        __half h1 = __float2half(v1);
                        __half2 hp; hp.x = h0; hp.y = h1;
                        __half2 lp;
                        lp.x = __float2half(v0 - __half2float(h0));
                        lp.y = __float2half(v1 - __half2float(h1));
                        *(__half2*)(outHi + (size_t)m * N + n) = hp;
                        *(__half2*)(outLo + (size_t)m * N + n) = lp;
                    }
                }
            }
        }
    }
}

// ---- persistent batched layer-1 GEMM: N=3328 = [y|d|z|t] ----
struct L1Out {
    __half* hi[4];
    __half* lo[4];
    const float* bias[4];
};
__global__ void __launch_bounds__(512, 1)
gemmL1(const __grid_constant__ CUtensorMap tAh, const __grid_constant__ CUtensorMap tAl,
       const __grid_constant__ CUtensorMap tBw,
       L1Out O, const float* __restrict__ yv, const float* __restrict__ dv,
       const float* __restrict__ wyd, const int* __restrict__ posmap)
{
    extern __shared__ char smraw[];
    uint32_t sb = smem_u32(smraw);
    uint32_t ab = (sb + 1023u) & ~1023u;
    const uint32_t mbar = ab + NSTAGE * STAGE_SZ;
    const int tid = threadIdx.x;
    const int wid = tid >> 5;
    const int lane = tid & 31;
    const int warp_m = wid & 3;
    const int warp_n = wid >> 2;
    const int nc = 32;
    const int ntN = 26;
    const int nTiles = 26 * 64;

    PERS_INIT()

    int tiles_mine = 0;
    for (int t = blockIdx.x; t < nTiles; t += gridDim.x) tiles_mine++;
    const long total = (long)tiles_mine * nc;

    int p_t = blockIdx.x, p_k = 0;
    if (tid == 0) {
        for (long i = 0; i < 3; i++) {
            PERS_ISSUE(p_t, p_k, (int)i)
            if (++p_k == nc) { p_k = 0; p_t += gridDim.x; }
        }
    }

    long g = 0;
    for (int t = blockIdx.x; t < nTiles; t += gridDim.x) {
        const int bm = (t / ntN) * 256;
        const int bnT = (t % ntN) * 128;
        const int seg = bnT >> 10;            // 0=y 1=d 2=z 3=t
        const int bn = bnT & 1023;
        float acc[4][4][4];
#pragma unroll
        for (int i = 0; i < 4; i++)
#pragma unroll
            for (int j = 0; j < 4; j++)
#pragma unroll
                for (int q = 0; q < 4; q++) acc[i][j][q] = 0.f;

        for (int ch = 0; ch < nc; ch++, g++) {
            int s = (int)(g & 3);
            MBARRIER_WAIT_PARITY(mbar + s * 8, (int)((g >> 2) & 1));
            compute_chunk(ab + s * STAGE_SZ, warp_m, warp_n, lane, acc);
            if (lane == 0) MBARRIER_ARRIVE(mbar + 32 + s * 8);
            if (tid == 0) {
                long j = g + 3;
                if (j < total) {
                    int s3 = (int)(j & 3);
                    if (j >= 4) MBARRIER_WAIT_PARITY(mbar + 32 + s3 * 8, (int)(((j >> 2) - 1) & 1));
                    PERS_ISSUE(p_t, p_k, s3)
                    if (++p_k == nc) { p_k = 0; p_t += gridDim.x; }
                }
            }
        }

        __half* oh = O.hi[seg];
        __half* ol = O.lo[seg];
        const float* bias = O.bias[seg];
        const bool isZ = (seg == 2);
        const int segN = (seg == 3) ? 256 : 1024;
        const int tgm = lane >> 2;
        const int tgn = (lane & 3) * 2;
#pragma unroll
        for (int mt = 0; mt < 4; mt++) {
#pragma unroll
            for (int dh = 0; dh < 2; dh++) {
                int m = bm + warp_m * 64 + mt * 16 + tgm + dh * 8;
                float ya = 0.f, da = 0.f;
                int mo = m;
                if (isZ) { ya = __ldg(yv + m); da = __ldg(dv + m); mo = __ldg(posmap + m); }
#pragma unroll
                for (int nt = 0; nt < 4; nt++) {
                    int n = bn + warp_n * 32 + nt * 8 + tgn;
                    float v0 = acc[mt][nt][dh * 2 + 0];
                    float v1 = acc[mt][nt][dh * 2 + 1];
                    float2 bb = *(const float2*)(bias + n);
                    v0 += bb.x; v1 += bb.y;
                    if (isZ) {
                        float2 w0 = *(const float2*)(wyd + n);
                        float2 w1 = *(const float2*)(wyd + 1024 + n);
                        v0 += ya * w0.x + da * w1.x;
                        v1 += ya * w0.y + da * w1.y;
                    }
                    v0 = elu_f(v0); v1 = elu_f(v1);
                    __half h0 = __float2half(v0);
                    __half h1 = __float2half(v1);
                    __half2 hp; hp.x = h0; hp.y = h1;
                    __half2 lp;
                    lp.x = __float2half(v0 - __half2float(h0));
                    lp.y = __float2half(v1 - __half2float(h1));
                    *(__half2*)(oh + (size_t)mo * segN + n) = hp;
                    *(__half2*)(ol + (size_t)mo * segN + n) = lp;
                }
            }
        }
    }
}

// ---- persistent merged layer-2 GEMM: 1536 tiles = 3 x 512 (y2, d2, z2) ----
__global__ void __launch_bounds__(512, 1)
gemmL2(const __grid_constant__ CUtensorMap tA0h, const __grid_constant__ CUtensorMap tA0l,
       const __grid_constant__ CUtensorMap tA1h, const __grid_constant__ CUtensorMap tA1l,
       const __grid_constant__ CUtensorMap tA2h, const __grid_constant__ CUtensorMap tA2l,
       const __grid_constant__ CUtensorMap tB0, const __grid_constant__ CUtensorMap tB1,
       const __grid_constant__ CUtensorMap tB2,
       const float* __restrict__ b0, const float* __restrict__ b1, const float* __restrict__ b2,
       float* __restrict__ fy, float* __restrict__ fd,
       __half* __restrict__ z2hi, __half* __restrict__ z2lo)
{
    extern __shared__ char smraw[];
    uint32_t sb = smem_u32(smraw);
    uint32_t ab = (sb + 1023u) & ~1023u;
    const uint32_t mbar = ab + NSTAGE * STAGE_SZ;
    const int tid = threadIdx.x;
    const int wid = tid >> 5;
    const int lane = tid & 31;
    const int warp_m = wid & 3;
    const int warp_n = wid >> 2;
    const int nc = 32;
    const int nTiles = 1536;

    const CUtensorMap* Ah[3] = { &tA0h, &tA1h, &tA2h };
    const CUtensorMap* Al[3] = { &tA0l, &tA1l, &tA2l };
    const CUtensorMap* Bw[3] = { &tB0, &tB1, &tB2 };
    const float* biases[3] = { b0, b1, b2 };

    PERS_INIT()

    int tiles_mine = 0;
    for (int t = blockIdx.x; t < nTiles; t += gridDim.x) tiles_mine++;
    const long total = (long)tiles_mine * nc;

    auto issue = [&](int pt, int pk, int stage) {
        int seg_ = pt >> 9, ts_ = pt & 511;
        int bm_ = (ts_ >> 3) * 256, bn_ = (ts_ & 7) * 128;
        uint32_t st_ = ab + stage * STAGE_SZ;
        uint32_t mb_ = mbar + stage * 8;
        MBARRIER_EXPECT_TX(mb_, CHUNK_BYTES);
        tma2d(st_ + S_AH, Ah[seg_], pk * 32, bm_, mb_);
        tma2d(st_ + S_AL, Al[seg_], pk * 32, bm_, mb_);
        tma2d(st_ + S_BW, Bw[seg_], pk * 32, bn_, mb_);
    };

    int p_t = blockIdx.x, p_k = 0;
    if (tid == 0) {
        for (long i = 0; i < 3; i++) {
            issue(p_t, p_k, (int)i);
            if (++p_k == nc) { p_k = 0; p_t += gridDim.x; }
        }
    }

    long g = 0;
    for (int t = blockIdx.x; t < nTiles; t += gridDim.x) {
        const int seg = t >> 9, ts = t & 511;
        const int bm = (ts >> 3) * 256, bn = (ts & 7) * 128;
        float acc[4][4][4];
#pragma unroll
        for (int i = 0; i < 4; i++)
#pragma unroll
            for (int j = 0; j < 4; j++)
#pragma unroll
                for (int q = 0; q < 4; q++) acc[i][j][q] = 0.f;

        for (int ch = 0; ch < nc; ch++, g++) {
            int s = (int)(g & 3);
            MBARRIER_WAIT_PARITY(mbar + s * 8, (int)((g >> 2) & 1));
            compute_chunk(ab + s * STAGE_SZ, warp_m, warp_n, lane, acc);
            if (lane == 0) MBARRIER_ARRIVE(mbar + 32 + s * 8);
            if (tid == 0) {
                long j = g + 3;
                if (j < total) {
                    int s3 = (int)(j & 3);
                    if (j >= 4) MBARRIER_WAIT_PARITY(mbar + 32 + s3 * 8, (int)(((j >> 2) - 1) & 1));
                    issue(p_t, p_k, s3);
                    if (++p_k == nc) { p_k = 0; p_t += gridDim.x; }
                }
            }
        }

        const float* bias = biases[seg];
        const int tgm = lane >> 2;
        const int tgn = (lane & 3) * 2;
#pragma unroll
        for (int mt = 0; mt < 4; mt++) {
#pragma unroll
            for (int dh = 0; dh < 2; dh++) {
                int m = bm + warp_m * 64 + mt * 16 + tgm + dh * 8;
#pragma unroll
                for (int nt = 0; nt < 4; nt++) {
                    int n = bn + warp_n * 32 + nt * 8 + tgn;
                    float v0 = acc[mt][nt][dh * 2 + 0];
                    float v1 = acc[mt][nt][dh * 2 + 1];
                    float2 bb = *(const float2*)(bias + n);
                    v0 = elu_f(v0 + bb.x); v1 = elu_f(v1 + bb.y);
                    if (seg < 2) {
                        float* o = seg ? fd : fy;
                        *(float2*)(o + (size_t)m * 1024 + n) = make_float2(v0, v1);
                    } else {
                        __half h0 = __float2half(v0);
                        __half h1 = __float2half(v1);
                        __half2 hp; hp.x = h0; hp.y = h1;
                        __half2 lp;
                        lp.x = __float2half(v0 - __half2float(h0));
                        lp.y = __float2half(v1 - __half2float(h1));
                        *(__half2*)(z2hi + (size_t)m * 1024 + n) = hp;
                        *(__half2*)(z2lo + (size_t)m * 1024 + n) = lp;
                    }
                }
            }
        }
    }
}

// ---- z head: grouped GEMM over gathered rows ----
__global__ void __launch_bounds__(512, 1)
zheadT(const __grid_constant__ CUtensorMap tAh, const __grid_constant__ CUtensorMap tAl,
       const __grid_constant__ CUtensorMap tBw,
       const float* __restrict__ zhb, float* __restrict__ out)
{
    const int grp = blockIdx.z;
    const int cnt = g_cnt[grp];
    const int m0 = blockIdx.y * 256;
    if (m0 >= cnt) return;
    const int base = g_off[grp];
    const int bn = blockIdx.x * 128;
    const int brow = grp * 512 + bn;
    const int arow = base + m0;

    extern __shared__ char smraw[];
    uint32_t sb = smem_u32(smraw);
    uint32_t ab = (sb + 1023u) & ~1023u;
    const uint32_t mbar = ab + NSTAGE * STAGE_SZ;
    const int tid = threadIdx.x;
    const int wid = tid >> 5;
    const int lane = tid & 31;
    const int warp_m = wid & 3;
    const int warp_n = wid >> 2;

    PERS_INIT()

    if (tid == 0) {
        for (int p = 0; p < 3; p++) {
            uint32_t st = ab + p * STAGE_SZ;
            uint32_t mb = mbar + p * 8;
            MBARRIER_EXPECT_TX(mb, CHUNK_BYTES);
            tma2d(st + S_AH, &tAh, p * 32, arow, mb);
            tma2d(st + S_AL, &tAl, p * 32, arow, mb);
            tma2d(st + S_BW, &tBw, p * 32, brow, mb);
        }
    }

    float acc[4][4][4];
#pragma unroll
    for (int i = 0; i < 4; i++)
#pragma unroll
        for (int j = 0; j < 4; j++)
#pragma unroll
            for (int q = 0; q < 4; q++) acc[i][j][q] = 0.f;

    for (int ch = 0; ch < 32; ch++) {
        int s = ch & 3;
        MBARRIER_WAIT_PARITY(mbar + s * 8, (ch >> 2) & 1);
        compute_chunk(ab + s * STAGE_SZ, warp_m, warp_n, lane, acc);
        if (lane == 0) MBARRIER_ARRIVE(mbar + 32 + s * 8);
        if (tid == 0 && ch + 3 < 32) {
            int s3 = (ch + 3) & 3;
            if (ch >= 1) MBARRIER_WAIT_PARITY(mbar + 32 + s3 * 8, (((ch + 3) >> 2) - 1) & 1);
            uint32_t st = ab + s3 * STAGE_SZ;
            uint32_t mb = mbar + s3 * 8;
            int k0 = (ch + 3) * 32;
            MBARRIER_EXPECT_TX(mb, CHUNK_BYTES);
            tma2d(st + S_AH, &tAh, k0, arow, mb);
            tma2d(st + S_AL, &tAl, k0, arow, mb);
            tma2d(st + S_BW, &tBw, k0, brow, mb);
        }
    }

    const int tgm = lane >> 2;
    const int tgn = (lane & 3) * 2;
#pragma unroll
    for (int mt = 0; mt < 4; mt++) {
#pragma unroll
        for (int dh = 0; dh < 2; dh++) {
            int mloc = warp_m * 64 + mt * 16 + tgm + dh * 8;
            int gi = m0 + mloc;
            if (gi >= cnt) continue;
            int rg = g_ridx[base + gi];
            float* op = out + (size_t)rg * OUTC + 11;
#pragma unroll
            for (int nt = 0; nt < 4; nt++) {
                int n = bn + warp_n * 32 + nt * 8 + tgn;
                float v0 = acc[mt][nt][dh * 2 + 0] + __ldg(zhb + grp * 512 + n);
                float v1 = acc[mt][nt][dh * 2 + 1] + __ldg(zhb + grp * 512 + n + 1);
                if (n < 256) {
                    v0 = fminf(fmaxf(v0, -100.f), 100.f);
                    v1 = fminf(fmaxf(v1, -100.f), 100.f);
                } else {
                    v0 = fminf(softplus_f(v0) + 0.001f, 100.f);
                    v1 = fminf(softplus_f(v1) + 0.001f, 100.f);
                }
                op[n] = v0;
                op[n + 1] = v1;
            }
        }
    }
}

// ========================= small head kernels (fp32) =========================
__global__ void thead_kernel(const float* __restrict__ hid, const float* __restrict__ tw2,
                             const float* __restrict__ tb2, float* __restrict__ out)
{
    int w = (blockIdx.x * blockDim.x + threadIdx.x) >> 5;
    int lane = threadIdx.x & 31;
    if (w >= BATCH) return;
    const float* hr = hid + (size_t)w * 256;
    float acc[7] = {0.f, 0.f, 0.f, 0.f, 0.f, 0.f, 0.f};
    for (int k = lane; k < 256; k += 32) {
        float h = hr[k];
        const float* wr = tw2 + k * 7;
#pragma unroll
        for (int j = 0; j < 7; j++) acc[j] = fmaf(h, wr[j], acc[j]);
    }
#pragma unroll
    for (int j = 0; j < 7; j++)
        for (int o = 16; o > 0; o >>= 1) acc[j] += __shfl_xor_sync(0xffffffffu, acc[j], o);
    if (lane == 0) {
#pragma unroll
        for (int j = 0; j < 7; j++) {
            float v = elu_f(acc[j] + tb2[j]);
            out[(size_t)w * OUTC + j] = fminf(fmaxf(v, -10.f), 10.f);
        }
    }
}
__global__ void head2_kernel(const float* __restrict__ hid, const int* __restrict__ t,
                             const float* __restrict__ hW, const float* __restrict__ hb,
                             float* __restrict__ out, int col0)
{
    int w = (blockIdx.x * blockDim.x + threadIdx.x) >> 5;
    int lane = threadIdx.x & 31;
    if (w >= BATCH) return;
    int tt = t[w];
    const float*  hr = hid + (size_t)w * 1024;
    const float2* wp = (const float2*)(hW + (size_t)tt * 2048);
    float a0 = 0.f, a1 = 0.f;
    for (int k = lane; k < 1024; k += 32) {
        float h = hr[k];
        float2 ww = wp[k];
        a0 = fmaf(h, ww.x, a0);
        a1 = fmaf(h, ww.y, a1);
    }
    for (int o = 16; o > 0; o >>= 1) {
        a0 += __shfl_xor_sync(0xffffffffu, a0, o);
        a1 += __shfl_xor_sync(0xffffffffu, a1, o);
    }
    if (lane == 0) {
        float loc = fminf(fmaxf(a0 + hb[tt * 2 + 0], -1e6f), 1e6f);
        float sc  = fminf(softplus_f(a1 + hb[tt * 2 + 1]) + 1e-3f, 1e6f);
        out[(size_t)w * OUTC + col0]     = loc;
        out[(size_t)w * OUTC + col0 + 1] = sc;
    }
}

// ========================= host-side tensormap builder =========================
typedef CUresult (*PFN_tmap)(CUtensorMap*, CUtensorMapDataType, cuuint32_t, void*,
                             const cuuint64_t*, const cuuint64_t*, const cuuint32_t*,
                             const cuuint32_t*, CUtensorMapInterleave, CUtensorMapSwizzle,
                             CUtensorMapL2promotion, CUtensorMapFloatOOBfill);
static PFN_tmap tmap_fn() {
    static PFN_tmap fn = nullptr;
    if (!fn) {
        cudaDriverEntryPointQueryResult qr;
        cudaGetDriverEntryPointByVersion("cuTensorMapEncodeTiled", (void**)&fn, 12000,
                                         cudaEnableDefault, &qr);
    }
    return fn;
}
static void make_map(CUtensorMap* m, const __half* base, unsigned long long inner,
                     unsigned long long outer, unsigned box_in, unsigned box_out) {
    cuuint64_t dims[2] = { inner, outer };
    cuuint64_t strides[1] = { inner * 2 };
    cuuint32_t box[2] = { box_in, box_out };
    cuuint32_t es[2] = { 1, 1 };
    tmap_fn()(m, CU_TENSOR_MAP_DATA_TYPE_FLOAT16, 2, (void*)base, dims, strides, box, es,
              CU_TENSOR_MAP_INTERLEAVE_NONE, CU_TENSOR_MAP_SWIZZLE_64B,
              CU_TENSOR_MAP_L2_PROMOTION_L2_128B, CU_TENSOR_MAP_FLOAT_OOB_FILL_NONE);
}

// ========================= launch =========================
extern "C" void kernel_launch(void* const* d_in, const int* in_sizes, int n_in,
                              void* d_out, int out_size)
{
    const float* x   = (const float*)d_in[0];
    const int*   t   = (const int*)  d_in[1];
    const float* yv  = (const float*)d_in[2];
    const float* dv  = (const float*)d_in[3];
    const float* tw0 = (const float*)d_in[4];
    const float* tb0 = (const float*)d_in[5];
    const float* tw1 = (const float*)d_in[6];
    const float* tb1 = (const float*)d_in[7];
    const float* tw2 = (const float*)d_in[8];
    const float* tb2 = (const float*)d_in[9];
    const float* yw0 = (const float*)d_in[10];
    const float* yb0 = (const float*)d_in[11];
    const float* yw1 = (const float*)d_in[12];
    const float* yb1 = (const float*)d_in[13];
    const float* yhW = (const float*)d_in[14];
    const float* yhb = (const float*)d_in[15];
    const float* dw0 = (const float*)d_in[16];
    const float* db0 = (const float*)d_in[17];
    const float* dw1 = (const float*)d_in[18];
    const float* db1 = (const float*)d_in[19];
    const float* dhW = (const float*)d_in[20];
    const float* dhb = (const float*)d_in[21];
    const float* zw0 = (const float*)d_in[22];
    const float* zb0 = (const float*)d_in[23];
    const float* zw1 = (const float*)d_in[24];
    const float* zb1 = (const float*)d_in[25];
    const float* zhW = (const float*)d_in[26];
    const float* zhb = (const float*)d_in[27];
    float* out = (float*)d_out;

    __half *xhi, *xlo, *y1hi, *y1lo, *d1hi, *d1lo, *z1hi, *z1lo, *z2hi, *z2lo, *t1hi, *t1lo, *wh;
    float *fy, *fd, *ft;
    int *posmap;
    cudaGetSymbolAddress((void**)&xhi, g_xhi);
    cudaGetSymbolAddress((void**)&xlo, g_xlo);
    cudaGetSymbolAddress((void**)&y1hi, g_y1hi);
    cudaGetSymbolAddress((void**)&y1lo, g_y1lo);
    cudaGetSymbolAddress((void**)&d1hi, g_d1hi);
    cudaGetSymbolAddress((void**)&d1lo, g_d1lo);
    cudaGetSymbolAddress((void**)&z1hi, g_z1hi);
    cudaGetSymbolAddress((void**)&z1lo, g_z1lo);
    cudaGetSymbolAddress((void**)&z2hi, g_z2hi);
    cudaGetSymbolAddress((void**)&z2lo, g_z2lo);
    cudaGetSymbolAddress((void**)&t1hi, g_t1hi);
    cudaGetSymbolAddress((void**)&t1lo, g_t1lo);
    cudaGetSymbolAddress((void**)&wh, g_wh);
    cudaGetSymbolAddress((void**)&fy, g_fy);
    cudaGetSymbolAddress((void**)&fd, g_fd);
    cudaGetSymbolAddress((void**)&ft, g_ft);
    cudaGetSymbolAddress((void**)&posmap, g_pos);

    static cudaStream_t s1, s2, s3;
    static cudaEvent_t eL1, eL2, eJ1, eJ2, eJ3;
    static bool init = false;
    if (!init) {
        cudaStreamCreateWithFlags(&s1, cudaStreamNonBlocking);
        cudaStreamCreateWithFlags(&s2, cudaStreamNonBlocking);
        cudaStreamCreateWithFlags(&s3, cudaStreamNonBlocking);
        cudaEventCreateWithFlags(&eL1, cudaEventDisableTiming);
        cudaEventCreateWithFlags(&eL2, cudaEventDisableTiming);
        cudaEventCreateWithFlags(&eJ1, cudaEventDisableTiming);
        cudaEventCreateWithFlags(&eJ2, cudaEventDisableTiming);
        cudaEventCreateWithFlags(&eJ3, cudaEventDisableTiming);
        cudaFuncSetAttribute((const void*)gemmT<true>,  cudaFuncAttributeMaxDynamicSharedMemorySize, SMEM_REQ);
        cudaFuncSetAttribute((const void*)gemmT<false>, cudaFuncAttributeMaxDynamicSharedMemorySize, SMEM_REQ);
        cudaFuncSetAttribute((const void*)gemmL1,       cudaFuncAttributeMaxDynamicSharedMemorySize, SMEM_REQ);
        cudaFuncSetAttribute((const void*)gemmL2,       cudaFuncAttributeMaxDynamicSharedMemorySize, SMEM_REQ);
        cudaFuncSetAttribute((const void*)zheadT,       cudaFuncAttributeMaxDynamicSharedMemorySize, SMEM_REQ);
        init = true;
    }

    static CUtensorMap M[18];
    make_map(&M[0],  xhi,  1024, BATCH, 32, 256);
    make_map(&M[1],  xlo,  1024, BATCH, 32, 256);
    make_map(&M[2],  y1hi, 1024, BATCH, 32, 256);
    make_map(&M[3],  y1lo, 1024, BATCH, 32, 256);
    make_map(&M[4],  d1hi, 1024, BATCH, 32, 256);
    make_map(&M[5],  d1lo, 1024, BATCH, 32, 256);
    make_map(&M[6],  z1hi, 1024, BATCH, 32, 256);
    make_map(&M[7],  z1lo, 1024, BATCH, 32, 256);
    make_map(&M[8],  z2hi, 1024, BATCH, 32, 256);
    make_map(&M[9],  z2lo, 1024, BATCH, 32, 256);
    make_map(&M[10], t1hi, 256,  BATCH, 32, 256);
    make_map(&M[11], t1lo, 256,  BATCH, 32, 256);
    make_map(&M[12], wh + OFF_TW1, 256,  256,  32, 128);
    make_map(&M[13], wh + OFF_L1,  1024, 3328, 32, 128);
    make_map(&M[14], wh + OFF_YW1, 1024, 1024, 32, 128);
    make_map(&M[15], wh + OFF_DW1, 1024, 1024, 32, 128);
    make_map(&M[16], wh + OFF_ZW1, 1024, 1024, 32, 128);
    make_map(&M[17], wh + OFF_ZHW, 1024, 3584, 32, 128);

    bucket_all<<<1, 1024>>>(t);
    xsplit_kernel<<<(BATCH * 1024 + 255) / 256, 256>>>(x, xhi, xlo, BATCH * 1024);
    WTab tab;
    tab.e[0]  = { tw1,            OFF_TW1,               256,  256 };
    tab.e[1]  = { yw0,            OFF_L1,                1024, 1024 };
    tab.e[2]  = { dw0,            OFF_L1 + 1048576ull,   1024, 1024 };
    tab.e[3]  = { zw0 + 2 * 1024, OFF_L1 + 2097152ull,   1024, 1024 };
    tab.e[4]  = { tw0,            OFF_L1 + 3145728ull,   1024, 256 };
    tab.e[5]  = { yw1,            OFF_YW1,               1024, 1024 };
    tab.e[6]  = { dw1,            OFF_DW1,               1024, 1024 };
    tab.e[7]  = { zw1,            OFF_ZW1,               1024, 1024 };
    for (int g = 0; g < 7; g++)
        tab.e[8 + g] = { zhW + (size_t)g * 1024 * 512,
                         (unsigned long long)(OFF_ZHW + (size_t)g * 524288), 1024, 512 };
    wconv_all<<<dim3(32, 32, 15), dim3(32, 8)>>>(tab, wh);

    // ---- L1 mega (y|d|z|t layer-1) ----
    L1Out O;
    O.hi[0] = y1hi; O.lo[0] = y1lo; O.bias[0] = yb0;
    O.hi[1] = d1hi; O.lo[1] = d1lo; O.bias[1] = db0;
    O.hi[2] = z1hi; O.lo[2] = z1lo; O.bias[2] = zb0;
    O.hi[3] = t1hi; O.lo[3] = t1lo; O.bias[3] = tb0;
    gemmL1<<<148, 512, SMEM_REQ>>>(M[0], M[1], M[13], O, yv, dv, zw0, posmap);
    cudaEventRecord(eL1, 0);

    // ---- L2 mega (y2 | d2 | z2) ----
    gemmL2<<<148, 512, SMEM_REQ>>>(M[2], M[3], M[4], M[5], M[6], M[7],
                                   M[14], M[15], M[16],
                                   yb1, db1, zb1, fy, fd, z2hi, z2lo);
    cudaEventRecord(eL2, 0);

    const int headBlocks = (BATCH * 32) / 256;

    // ---- tails on streams ----
    cudaStreamWaitEvent(s1, eL1, 0);
    gemmT<true><<<128, 512, SMEM_REQ, s1>>>(M[10], M[11], M[12], tb1, 256, 256,
                                            ft, nullptr, nullptr, 2, 128);
    thead_kernel<<<headBlocks, 256, 0, s1>>>(ft, tw2, tb2, out);
    cudaEventRecord(eJ1, s1);

    cudaStreamWaitEvent(s2, eL2, 0);
    head2_kernel<<<headBlocks, 256, 0, s2>>>(fy, t, yhW, yhb, out, 7);
    head2_kernel<<<headBlocks, 256, 0, s2>>>(fd, t, dhW, dhb, out, 9);
    cudaEventRecord(eJ2, s2);

    cudaStreamWaitEvent(s3, eL2, 0);
    zheadT<<<dim3(4, 64, 7), 512, SMEM_REQ, s3>>>(M[8], M[9], M[17], zhb, out);
    cudaEventRecord(eJ3, s3);

    cudaStreamWaitEvent(0, eJ1, 0);
    cudaStreamWaitEvent(0, eJ2, 0);
    cudaStreamWaitEvent(0, eJ3, 0);
}

// round 13
// speedup vs baseline: 1.9850x; 1.5212x over previous
#include <cuda_runtime.h>
#include <cuda.h>
#include <cuda_fp16.h>
#include <cstdint>
#include <math.h>

#define BATCH 16384
#define OUTC  523   // 7 + 4 + 512

// ========================= PTX helpers (baseline sm_90-level, no arch-suffix) =========================
__device__ __forceinline__ uint32_t smem_u32(const void* p) {
    uint32_t a;
    asm("{ .reg .u64 t; cvta.to.shared.u64 t, %1; cvt.u32.u64 %0, t; }" : "=r"(a) : "l"(p));
    return a;
}
__device__ __forceinline__ void ldmx4(uint32_t& r0, uint32_t& r1, uint32_t& r2, uint32_t& r3, uint32_t addr) {
    asm volatile("ldmatrix.sync.aligned.m8n8.x4.shared.b16 {%0,%1,%2,%3}, [%4];"
                 : "=r"(r0), "=r"(r1), "=r"(r2), "=r"(r3) : "r"(addr));
}
__device__ __forceinline__ void mma16816(float* c, const uint32_t* a, uint32_t b0, uint32_t b1) {
    asm volatile("mma.sync.aligned.m16n8k16.row.col.f32.f16.f16.f32 "
                 "{%0,%1,%2,%3}, {%4,%5,%6,%7}, {%8,%9}, {%0,%1,%2,%3};"
                 : "+f"(c[0]), "+f"(c[1]), "+f"(c[2]), "+f"(c[3])
                 : "r"(a[0]), "r"(a[1]), "r"(a[2]), "r"(a[3]), "r"(b0), "r"(b1));
}
// SW64 swizzle: atom = 8 rows x 64B; conflict-free ldmatrix for 64B-row tiles
__device__ __forceinline__ uint32_t swz64(uint32_t off) { return off ^ ((off >> 3) & 0x30); }

__device__ __forceinline__ void tma2d(uint32_t dst, const CUtensorMap* map, int cx, int cy, uint32_t mbar) {
    asm volatile("cp.async.bulk.tensor.2d.shared::cta.global.tile.mbarrier::complete_tx::bytes "
                 "[%0], [%1, {%2, %3}], [%4];"
                 :: "r"(dst), "l"(map), "r"(cx), "r"(cy), "r"(mbar) : "memory");
}
#define MBARRIER_INIT(addr, cnt) \
    asm volatile("mbarrier.init.shared.b64 [%0], %1;" :: "r"((uint32_t)(addr)), "r"((uint32_t)(cnt)) : "memory")
#define MBARRIER_ARRIVE(addr) \
    asm volatile("mbarrier.arrive.shared.b64 _, [%0];" :: "r"((uint32_t)(addr)) : "memory")
#define MBARRIER_EXPECT_TX(addr, bytes) \
    asm volatile("mbarrier.arrive.expect_tx.shared.b64 _, [%0], %1;" \
        :: "r"((uint32_t)(addr)), "r"((uint32_t)(bytes)) : "memory")
#define MBARRIER_WAIT_PARITY(mbar_smem_addr, phase_parity) do { \
    uint32_t _mbar = (uint32_t)(mbar_smem_addr); \
    uint32_t _parity = (uint32_t)(phase_parity); \
    uint32_t _done; \
    asm volatile("{\n\t.reg .pred p;\n\t" \
        "mbarrier.try_wait.parity.acquire.cta.shared::cta.b64 p, [%1], %2;\n\t" \
        "selp.b32 %0, 1, 0, p;\n\t}" : "=r"(_done) : "r"(_mbar), "r"(_parity) : "memory"); \
    if (!_done) { \
        asm volatile("{\n\t.reg .pred P1;\n\t" \
            "WAIT_LOOP_%=:\n\t" \
            "mbarrier.try_wait.parity.acquire.cta.shared::cta.b64 P1, [%0], %1, 0x989680;\n\t" \
            "@P1 bra.uni WAIT_DONE_%=;\n\t" \
            "bra.uni WAIT_LOOP_%=;\n\t" \
            "WAIT_DONE_%=:\n\t}" :: "r"(_mbar), "r"(_parity) : "memory"); \
    } \
} while(0)

// ========================= scratch =========================
__device__ __align__(1024) __half g_x[BATCH * 1024];
__device__ __align__(1024) __half g_y1[BATCH * 1024];
__device__ __align__(1024) __half g_d1[BATCH * 1024];
__device__ __align__(1024) __half g_z1[BATCH * 1024];   // bucket order
__device__ __align__(1024) __half g_z2[BATCH * 1024];   // bucket order
__device__ __align__(1024) __half g_t1[BATCH * 256];
__device__ float g_fy[BATCH * 1024];
__device__ float g_fd[BATCH * 1024];
__device__ float g_ft[BATCH * 256];
__device__ __align__(1024) __half g_wh[10300000];       // single-fp16 weight pool
__device__ int g_ridx[BATCH];
__device__ int g_pos[BATCH];
__device__ int g_cnt[8];
__device__ int g_off[8];

// weight-pool offsets (elements)
#define OFF_TW1 0             // [256,256]
#define OFF_L1  65536         // [3328,1024]: yw0|dw0|zw0'|tw0
#define OFF_YW1 3473408
#define OFF_DW1 4521984
#define OFF_ZW1 5570560
#define OFF_ZHW 6619136       // [3584,1024]

__device__ __forceinline__ float elu_f(float v) { return v > 0.f ? v : expm1f(v); }
__device__ __forceinline__ float softplus_f(float v) {
    return fmaxf(v, 0.f) + log1pf(expf(-fabsf(v)));
}

// ========================= fused bucketing =========================
__global__ void bucket_all(const int* __restrict__ t) {
    __shared__ int scnt[8];
    __shared__ int scur[8];
    int tid = threadIdx.x;
    if (tid < 8) scnt[tid] = 0;
    __syncthreads();
    for (int i = tid; i < BATCH; i += 1024) atomicAdd(&scnt[t[i]], 1);
    __syncthreads();
    if (tid == 0) {
        int s = 0;
        for (int k = 0; k < 7; k++) { g_cnt[k] = scnt[k]; g_off[k] = s; scur[k] = s; s += scnt[k]; }
    }
    __syncthreads();
    for (int i = tid; i < BATCH; i += 1024) {
        int p = atomicAdd(&scur[t[i]], 1);
        g_ridx[p] = i;
        g_pos[i] = p;
    }
}

// ========================= preprocessing =========================
__global__ void xconv_kernel(const float* __restrict__ x, __half* __restrict__ o, int n) {
    int i = blockIdx.x * blockDim.x + threadIdx.x;
    if (i < n) o[i] = __float2half(x[i]);
}
struct WEnt { const float* p; unsigned long long off; int kd, n; };
struct WTab { WEnt e[15]; };
__global__ void wconv_all(WTab tab, __half* __restrict__ wp) {
    WEnt E = tab.e[blockIdx.z];
    int n0 = blockIdx.x * 32, k0 = blockIdx.y * 32;
    if (n0 >= E.n || k0 >= E.kd) return;
    __shared__ float tile[32][33];
    int tx = threadIdx.x, ty = threadIdx.y;
    for (int i = ty; i < 32; i += 8)
        tile[i][tx] = E.p[(size_t)(k0 + i) * E.n + n0 + tx];
    __syncthreads();
    __half* W = wp + E.off;
    for (int i = ty; i < 32; i += 8)
        W[(size_t)(n0 + i) * E.kd + k0 + tx] = __float2half(tile[tx][i]);
}

// ========================= TMA-fed 1xFP16 mma.sync GEMM core =========================
// CTA tile 256x128, K-chunk 32 (64B rows, SW64), 512 threads = 16 warps, warp tile 64x32.
// Plain fp16 GEMM, fp32 accumulate. Persistent tile loop, 4 TMA stages.
#define S_A 0
#define S_B 16384
#define STAGE_SZ 24576
#define CHUNK_BYTES 24576u
#define NSTAGE 4
#define SMEM_REQ 99392

__device__ __forceinline__ void compute_chunk(uint32_t st, int warp_m, int warp_n, int lane,
                                              float acc[4][4][4])
{
    const int lrow = lane & 7;
    const int lmat = lane >> 3;
#pragma unroll
    for (int ks = 0; ks < 2; ks++) {
        uint32_t bw[8];
#pragma unroll
        for (int p = 0; p < 2; p++) {
            int ntile = p * 2 + (lmat >> 1);
            int half_ = lmat & 1;
            uint32_t off = (uint32_t)((warp_n * 32 + ntile * 8 + lrow) * 64 + (ks * 16 + half_ * 8) * 2);
            uint32_t a = swz64(off);
            ldmx4(bw[p * 4 + 0], bw[p * 4 + 1], bw[p * 4 + 2], bw[p * 4 + 3], st + S_B + a);
        }
#pragma unroll
        for (int mt = 0; mt < 4; mt++) {
            uint32_t ar[4];
            uint32_t off = (uint32_t)((warp_m * 64 + mt * 16 + (lmat & 1) * 8 + lrow) * 64
                                      + (ks * 16 + (lmat >> 1) * 8) * 2);
            uint32_t a = swz64(off);
            ldmx4(ar[0], ar[1], ar[2], ar[3], st + S_A + a);
#pragma unroll
            for (int nt = 0; nt < 4; nt++)
                mma16816(acc[mt][nt], ar, bw[nt * 2], bw[nt * 2 + 1]);
        }
    }
}

#define PERS_INIT()                                                              \
    if (tid == 0) {                                                              \
        for (int s = 0; s < NSTAGE; s++) {                                       \
            MBARRIER_INIT(mbar + s * 8, 1);                                      \
            MBARRIER_INIT(mbar + 32 + s * 8, 16);                                \
        }                                                                        \
    }                                                                            \
    __syncthreads();

#define PERS_ISSUE(PT, PK, STAGE)                                                \
    {                                                                            \
        uint32_t st_ = ab + (STAGE) * STAGE_SZ;                                  \
        uint32_t mb_ = mbar + (STAGE) * 8;                                       \
        int pbm_ = ((PT) / ntN) * 256, pbn_ = ((PT) % ntN) * 128;                \
        MBARRIER_EXPECT_TX(mb_, CHUNK_BYTES);                                    \
        tma2d(st_ + S_A, &tA, (PK) * 32, pbm_, mb_);                             \
        tma2d(st_ + S_B, &tB, (PK) * 32, pbn_, mb_);                             \
    }

// ---- persistent GEMM: C = elu(A@Wt^T + bias), output f32 or fp16 ----
template<bool OUT_F32>
__global__ void __launch_bounds__(512, 1)
gemmT(const __grid_constant__ CUtensorMap tA, const __grid_constant__ CUtensorMap tB,
      const float* __restrict__ bias, int N, int Kd,
      float* __restrict__ outF, __half* __restrict__ outH,
      int ntN, int nTiles)
{
    extern __shared__ char smraw[];
    uint32_t sb = smem_u32(smraw);
    uint32_t ab = (sb + 1023u) & ~1023u;
    const uint32_t mbar = ab + NSTAGE * STAGE_SZ;
    const int tid = threadIdx.x;
    const int wid = tid >> 5;
    const int lane = tid & 31;
    const int warp_m = wid & 3;
    const int warp_n = wid >> 2;
    const int nc = Kd >> 5;

    if (blockIdx.x >= (unsigned)nTiles) return;
    PERS_INIT()

    int tiles_mine = 0;
    for (int t = blockIdx.x; t < nTiles; t += gridDim.x) tiles_mine++;
    const long total = (long)tiles_mine * nc;

    int p_t = blockIdx.x, p_k = 0;
    if (tid == 0) {
        long lim = total < 3 ? total : 3;
        for (long i = 0; i < lim; i++) {
            PERS_ISSUE(p_t, p_k, (int)i)
            if (++p_k == nc) { p_k = 0; p_t += gridDim.x; }
        }
    }

    long g = 0;
    for (int t = blockIdx.x; t < nTiles; t += gridDim.x) {
        const int bm = (t / ntN) * 256, bn = (t % ntN) * 128;
        float acc[4][4][4];
#pragma unroll
        for (int i = 0; i < 4; i++)
#pragma unroll
            for (int j = 0; j < 4; j++)
#pragma unroll
                for (int q = 0; q < 4; q++) acc[i][j][q] = 0.f;

        for (int ch = 0; ch < nc; ch++, g++) {
            int s = (int)(g & 3);
            MBARRIER_WAIT_PARITY(mbar + s * 8, (int)((g >> 2) & 1));
            compute_chunk(ab + s * STAGE_SZ, warp_m, warp_n, lane, acc);
            if (lane == 0) MBARRIER_ARRIVE(mbar + 32 + s * 8);
            if (tid == 0) {
                long j = g + 3;
                if (j < total) {
                    int s3 = (int)(j & 3);
                    if (j >= 4) MBARRIER_WAIT_PARITY(mbar + 32 + s3 * 8, (int)(((j >> 2) - 1) & 1));
                    PERS_ISSUE(p_t, p_k, s3)
                    if (++p_k == nc) { p_k = 0; p_t += gridDim.x; }
                }
            }
        }

        const int tgm = lane >> 2;
        const int tgn = (lane & 3) * 2;
#pragma unroll
        for (int mt = 0; mt < 4; mt++) {
#pragma unroll
            for (int dh = 0; dh < 2; dh++) {
                int m = bm + warp_m * 64 + mt * 16 + tgm + dh * 8;
#pragma unroll
                for (int nt = 0; nt < 4; nt++) {
                    int n = bn + warp_n * 32 + nt * 8 + tgn;
                    float v0 = acc[mt][nt][dh * 2 + 0];
                    float v1 = acc[mt][nt][dh * 2 + 1];
                    float2 bb = *(const float2*)(bias + n);
                    v0 = elu_f(v0 + bb.x); v1 = elu_f(v1 + bb.y);
                    if (OUT_F32) {
                        *(float2*)(outF + (size_t)m * N + n) = make_float2(v0, v1);
                    } else {
                        __half2 hp; hp.x = __float2half(v0); hp.y = __float2half(v1);
                        *(__half2*)(outH + (size_t)m * N + n) = hp;
                    }
                }
            }
        }
    }
}

// ---- persistent batched layer-1 GEMM: N=3328 = [y|d|z|t] ----
struct L1Out {
    __half* o[4];
    const float* bias[4];
};
__global__ void __launch_bounds__(512, 1)
gemmL1(const __grid_constant__ CUtensorMap tA, const __grid_constant__ CUtensorMap tB,
       L1Out O, const float* __restrict__ yv, const float* __restrict__ dv,
       const float* __restrict__ wyd, const int* __restrict__ posmap)
{
    extern __shared__ char smraw[];
    uint32_t sb = smem_u32(smraw);
    uint32_t ab = (sb + 1023u) & ~1023u;
    const uint32_t mbar = ab + NSTAGE * STAGE_SZ;
    const int tid = threadIdx.x;
    const int wid = tid >> 5;
    const int lane = tid & 31;
    const int warp_m = wid & 3;
    const int warp_n = wid >> 2;
    const int nc = 32;
    const int ntN = 26;
    const int nTiles = 26 * 64;

    PERS_INIT()

    int tiles_mine = 0;
    for (int t = blockIdx.x; t < nTiles; t += gridDim.x) tiles_mine++;
    const long total = (long)tiles_mine * nc;

    int p_t = blockIdx.x, p_k = 0;
    if (tid == 0) {
        for (long i = 0; i < 3; i++) {
            PERS_ISSUE(p_t, p_k, (int)i)
            if (++p_k == nc) { p_k = 0; p_t += gridDim.x; }
        }
    }

    long g = 0;
    for (int t = blockIdx.x; t < nTiles; t += gridDim.x) {
        const int bm = (t / ntN) * 256;
        const int bnT = (t % ntN) * 128;
        const int seg = bnT >> 10;            // 0=y 1=d 2=z 3=t
        const int bn = bnT & 1023;
        float acc[4][4][4];
#pragma unroll
        for (int i = 0; i < 4; i++)
#pragma unroll
            for (int j = 0; j < 4; j++)
#pragma unroll
                for (int q = 0; q < 4; q++) acc[i][j][q] = 0.f;

        for (int ch = 0; ch < nc; ch++, g++) {
            int s = (int)(g & 3);
            MBARRIER_WAIT_PARITY(mbar + s * 8, (int)((g >> 2) & 1));
            compute_chunk(ab + s * STAGE_SZ, warp_m, warp_n, lane, acc);
            if (lane == 0) MBARRIER_ARRIVE(mbar + 32 + s * 8);
            if (tid == 0) {
                long j = g + 3;
                if (j < total) {
                    int s3 = (int)(j & 3);
                    if (j >= 4) MBARRIER_WAIT_PARITY(mbar + 32 + s3 * 8, (int)(((j >> 2) - 1) & 1));
                    PERS_ISSUE(p_t, p_k, s3)
                    if (++p_k == nc) { p_k = 0; p_t += gridDim.x; }
                }
            }
        }

        __half* oh = O.o[seg];
        const float* bias = O.bias[seg];
        const bool isZ = (seg == 2);
        const int segN = (seg == 3) ? 256 : 1024;
        const int tgm = lane >> 2;
        const int tgn = (lane & 3) * 2;
#pragma unroll
        for (int mt = 0; mt < 4; mt++) {
#pragma unroll
            for (int dh = 0; dh < 2; dh++) {
                int m = bm + warp_m * 64 + mt * 16 + tgm + dh * 8;
                float ya = 0.f, da = 0.f;
                int mo = m;
                if (isZ) { ya = __ldg(yv + m); da = __ldg(dv + m); mo = __ldg(posmap + m); }
#pragma unroll
                for (int nt = 0; nt < 4; nt++) {
                    int n = bn + warp_n * 32 + nt * 8 + tgn;
                    float v0 = acc[mt][nt][dh * 2 + 0];
                    float v1 = acc[mt][nt][dh * 2 + 1];
                    float2 bb = *(const float2*)(bias + n);
                    v0 += bb.x; v1 += bb.y;
                    if (isZ) {
                        float2 w0 = *(const float2*)(wyd + n);
                        float2 w1 = *(const float2*)(wyd + 1024 + n);
                        v0 += ya * w0.x + da * w1.x;
                        v1 += ya * w0.y + da * w1.y;
                    }
                    v0 = elu_f(v0); v1 = elu_f(v1);
                    __half2 hp; hp.x = __float2half(v0); hp.y = __float2half(v1);
                    *(__half2*)(oh + (size_t)mo * segN + n) = hp;
                }
            }
        }
    }
}

// ---- persistent merged layer-2 GEMM: 1536 tiles = 3 x 512 (y2, d2, z2) ----
__global__ void __launch_bounds__(512, 1)
gemmL2(const __grid_constant__ CUtensorMap tA0, const __grid_constant__ CUtensorMap tA1,
       const __grid_constant__ CUtensorMap tA2,
       const __grid_constant__ CUtensorMap tB0, const __grid_constant__ CUtensorMap tB1,
       const __grid_constant__ CUtensorMap tB2,
       const float* __restrict__ b0, const float* __restrict__ b1, const float* __restrict__ b2,
       float* __restrict__ fy, float* __restrict__ fd, __half* __restrict__ z2)
{
    extern __shared__ char smraw[];
    uint32_t sb = smem_u32(smraw);
    uint32_t ab = (sb + 1023u) & ~1023u;
    const uint32_t mbar = ab + NSTAGE * STAGE_SZ;
    const int tid = threadIdx.x;
    const int wid = tid >> 5;
    const int lane = tid & 31;
    const int warp_m = wid & 3;
    const int warp_n = wid >> 2;
    const int nc = 32;
    const int nTiles = 1536;

    const CUtensorMap* Am[3] = { &tA0, &tA1, &tA2 };
    const CUtensorMap* Bm[3] = { &tB0, &tB1, &tB2 };
    const float* biases[3] = { b0, b1, b2 };

    PERS_INIT()

    int tiles_mine = 0;
    for (int t = blockIdx.x; t < nTiles; t += gridDim.x) tiles_mine++;
    const long total = (long)tiles_mine * nc;

    auto issue = [&](int pt, int pk, int stage) {
        int seg_ = pt >> 9, ts_ = pt & 511;
        int bm_ = (ts_ >> 3) * 256, bn_ = (ts_ & 7) * 128;
        uint32_t st_ = ab + stage * STAGE_SZ;
        uint32_t mb_ = mbar + stage * 8;
        MBARRIER_EXPECT_TX(mb_, CHUNK_BYTES);
        tma2d(st_ + S_A, Am[seg_], pk * 32, bm_, mb_);
        tma2d(st_ + S_B, Bm[seg_], pk * 32, bn_, mb_);
    };

    int p_t = blockIdx.x, p_k = 0;
    if (tid == 0) {
        for (long i = 0; i < 3; i++) {
            issue(p_t, p_k, (int)i);
            if (++p_k == nc) { p_k = 0; p_t += gridDim.x; }
        }
    }

    long g = 0;
    for (int t = blockIdx.x; t < nTiles; t += gridDim.x) {
        const int seg = t >> 9, ts = t & 511;
        const int bm = (ts >> 3) * 256, bn = (ts & 7) * 128;
        float acc[4][4][4];
#pragma unroll
        for (int i = 0; i < 4; i++)
#pragma unroll
            for (int j = 0; j < 4; j++)
#pragma unroll
                for (int q = 0; q < 4; q++) acc[i][j][q] = 0.f;

        for (int ch = 0; ch < nc; ch++, g++) {
            int s = (int)(g & 3);
            MBARRIER_WAIT_PARITY(mbar + s * 8, (int)((g >> 2) & 1));
            compute_chunk(ab + s * STAGE_SZ, warp_m, warp_n, lane, acc);
            if (lane == 0) MBARRIER_ARRIVE(mbar + 32 + s * 8);
            if (tid == 0) {
                long j = g + 3;
                if (j < total) {
                    int s3 = (int)(j & 3);
                    if (j >= 4) MBARRIER_WAIT_PARITY(mbar + 32 + s3 * 8, (int)(((j >> 2) - 1) & 1));
                    issue(p_t, p_k, s3);
                    if (++p_k == nc) { p_k = 0; p_t += gridDim.x; }
                }
            }
        }

        const float* bias = biases[seg];
        const int tgm = lane >> 2;
        const int tgn = (lane & 3) * 2;
#pragma unroll
        for (int mt = 0; mt < 4; mt++) {
#pragma unroll
            for (int dh = 0; dh < 2; dh++) {
                int m = bm + warp_m * 64 + mt * 16 + tgm + dh * 8;
#pragma unroll
                for (int nt = 0; nt < 4; nt++) {
                    int n = bn + warp_n * 32 + nt * 8 + tgn;
                    float v0 = acc[mt][nt][dh * 2 + 0];
                    float v1 = acc[mt][nt][dh * 2 + 1];
                    float2 bb = *(const float2*)(bias + n);
                    v0 = elu_f(v0 + bb.x); v1 = elu_f(v1 + bb.y);
                    if (seg < 2) {
                        float* o = seg ? fd : fy;
                        *(float2*)(o + (size_t)m * 1024 + n) = make_float2(v0, v1);
                    } else {
                        __half2 hp; hp.x = __float2half(v0); hp.y = __float2half(v1);
                        *(__half2*)(z2 + (size_t)m * 1024 + n) = hp;
                    }
                }
            }
        }
    }
}

// ---- z head: grouped GEMM over gathered rows ----
__global__ void __launch_bounds__(512, 1)
zheadT(const __grid_constant__ CUtensorMap tA, const __grid_constant__ CUtensorMap tB,
       const float* __restrict__ zhb, float* __restrict__ out)
{
    const int grp = blockIdx.z;
    const int cnt = g_cnt[grp];
    const int m0 = blockIdx.y * 256;
    if (m0 >= cnt) return;
    const int base = g_off[grp];
    const int bn = blockIdx.x * 128;
    const int brow = grp * 512 + bn;
    const int arow = base + m0;

    extern __shared__ char smraw[];
    uint32_t sb = smem_u32(smraw);
    uint32_t ab = (sb + 1023u) & ~1023u;
    const uint32_t mbar = ab + NSTAGE * STAGE_SZ;
    const int tid = threadIdx.x;
    const int wid = tid >> 5;
    const int lane = tid & 31;
    const int warp_m = wid & 3;
    const int warp_n = wid >> 2;

    PERS_INIT()

    if (tid == 0) {
        for (int p = 0; p < 3; p++) {
            uint32_t st = ab + p * STAGE_SZ;
            uint32_t mb = mbar + p * 8;
            MBARRIER_EXPECT_TX(mb, CHUNK_BYTES);
            tma2d(st + S_A, &tA, p * 32, arow, mb);
            tma2d(st + S_B, &tB, p * 32, brow, mb);
        }
    }

    float acc[4][4][4];
#pragma unroll
    for (int i = 0; i < 4; i++)
#pragma unroll
        for (int j = 0; j < 4; j++)
#pragma unroll
            for (int q = 0; q < 4; q++) acc[i][j][q] = 0.f;

    for (int ch = 0; ch < 32; ch++) {
        int s = ch & 3;
        MBARRIER_WAIT_PARITY(mbar + s * 8, (ch >> 2) & 1);
        compute_chunk(ab + s * STAGE_SZ, warp_m, warp_n, lane, acc);
        if (lane == 0) MBARRIER_ARRIVE(mbar + 32 + s * 8);
        if (tid == 0 && ch + 3 < 32) {
            int s3 = (ch + 3) & 3;
            if (ch >= 1) MBARRIER_WAIT_PARITY(mbar + 32 + s3 * 8, (((ch + 3) >> 2) - 1) & 1);
            uint32_t st = ab + s3 * STAGE_SZ;
            uint32_t mb = mbar + s3 * 8;
            int k0 = (ch + 3) * 32;
            MBARRIER_EXPECT_TX(mb, CHUNK_BYTES);
            tma2d(st + S_A, &tA, k0, arow, mb);
            tma2d(st + S_B, &tB, k0, brow, mb);
        }
    }

    const int tgm = lane >> 2;
    const int tgn = (lane & 3) * 2;
#pragma unroll
    for (int mt = 0; mt < 4; mt++) {
#pragma unroll
        for (int dh = 0; dh < 2; dh++) {
            int mloc = warp_m * 64 + mt * 16 + tgm + dh * 8;
            int gi = m0 + mloc;
            if (gi >= cnt) continue;
            int rg = g_ridx[base + gi];
            float* op = out + (size_t)rg * OUTC + 11;
#pragma unroll
            for (int nt = 0; nt < 4; nt++) {
                int n = bn + warp_n * 32 + nt * 8 + tgn;
                float v0 = acc[mt][nt][dh * 2 + 0] + __ldg(zhb + grp * 512 + n);
                float v1 = acc[mt][nt][dh * 2 + 1] + __ldg(zhb + grp * 512 + n + 1);
                if (n < 256) {
                    v0 = fminf(fmaxf(v0, -100.f), 100.f);
                    v1 = fminf(fmaxf(v1, -100.f), 100.f);
                } else {
                    v0 = fminf(softplus_f(v0) + 0.001f, 100.f);
                    v1 = fminf(softplus_f(v1) + 0.001f, 100.f);
                }
                op[n] = v0;
                op[n + 1] = v1;
            }
        }
    }
}

// ========================= small head kernels (fp32) =========================
__global__ void thead_kernel(const float* __restrict__ hid, const float* __restrict__ tw2,
                             const float* __restrict__ tb2, float* __restrict__ out)
{
    int w = (blockIdx.x * blockDim.x + threadIdx.x) >> 5;
    int lane = threadIdx.x & 31;
    if (w >= BATCH) return;
    const float* hr = hid + (size_t)w * 256;
    float acc[7] = {0.f, 0.f, 0.f, 0.f, 0.f, 0.f, 0.f};
    for (int k = lane; k < 256; k += 32) {
        float h = hr[k];
        const float* wr = tw2 + k * 7;
#pragma unroll
        for (int j = 0; j < 7; j++) acc[j] = fmaf(h, wr[j], acc[j]);
    }
#pragma unroll
    for (int j = 0; j < 7; j++)
        for (int o = 16; o > 0; o >>= 1) acc[j] += __shfl_xor_sync(0xffffffffu, acc[j], o);
    if (lane == 0) {
#pragma unroll
        for (int j = 0; j < 7; j++) {
            float v = elu_f(acc[j] + tb2[j]);
            out[(size_t)w * OUTC + j] = fminf(fmaxf(v, -10.f), 10.f);
        }
    }
}
__global__ void head2_kernel(const float* __restrict__ hid, const int* __restrict__ t,
                             const float* __restrict__ hW, const float* __restrict__ hb,
                             float* __restrict__ out, int col0)
{
    int w = (blockIdx.x * blockDim.x + threadIdx.x) >> 5;
    int lane = threadIdx.x & 31;
    if (w >= BATCH) return;
    int tt = t[w];
    const float*  hr = hid + (size_t)w * 1024;
    const float2* wp = (const float2*)(hW + (size_t)tt * 2048);
    float a0 = 0.f, a1 = 0.f;
    for (int k = lane; k < 1024; k += 32) {
        float h = hr[k];
        float2 ww = wp[k];
        a0 = fmaf(h, ww.x, a0);
        a1 = fmaf(h, ww.y, a1);
    }
    for (int o = 16; o > 0; o >>= 1) {
        a0 += __shfl_xor_sync(0xffffffffu, a0, o);
        a1 += __shfl_xor_sync(0xffffffffu, a1, o);
    }
    if (lane == 0) {
        float loc = fminf(fmaxf(a0 + hb[tt * 2 + 0], -1e6f), 1e6f);
        float sc  = fminf(softplus_f(a1 + hb[tt * 2 + 1]) + 1e-3f, 1e6f);
        out[(size_t)w * OUTC + col0]     = loc;
        out[(size_t)w * OUTC + col0 + 1] = sc;
    }
}

// ========================= host-side tensormap builder =========================
typedef CUresult (*PFN_tmap)(CUtensorMap*, CUtensorMapDataType, cuuint32_t, void*,
                             const cuuint64_t*, const cuuint64_t*, const cuuint32_t*,
                             const cuuint32_t*, CUtensorMapInterleave, CUtensorMapSwizzle,
                             CUtensorMapL2promotion, CUtensorMapFloatOOBfill);
static PFN_tmap tmap_fn() {
    static PFN_tmap fn = nullptr;
    if (!fn) {
        cudaDriverEntryPointQueryResult qr;
        cudaGetDriverEntryPointByVersion("cuTensorMapEncodeTiled", (void**)&fn, 12000,
                                         cudaEnableDefault, &qr);
    }
    return fn;
}
static void make_map(CUtensorMap* m, const __half* base, unsigned long long inner,
                     unsigned long long outer, unsigned box_in, unsigned box_out) {
    cuuint64_t dims[2] = { inner, outer };
    cuuint64_t strides[1] = { inner * 2 };
    cuuint32_t box[2] = { box_in, box_out };
    cuuint32_t es[2] = { 1, 1 };
    tmap_fn()(m, CU_TENSOR_MAP_DATA_TYPE_FLOAT16, 2, (void*)base, dims, strides, box, es,
              CU_TENSOR_MAP_INTERLEAVE_NONE, CU_TENSOR_MAP_SWIZZLE_64B,
              CU_TENSOR_MAP_L2_PROMOTION_L2_128B, CU_TENSOR_MAP_FLOAT_OOB_FILL_NONE);
}

// ========================= launch =========================
extern "C" void kernel_launch(void* const* d_in, const int* in_sizes, int n_in,
                              void* d_out, int out_size)
{
    const float* x   = (const float*)d_in[0];
    const int*   t   = (const int*)  d_in[1];
    const float* yv  = (const float*)d_in[2];
    const float* dv  = (const float*)d_in[3];
    const float* tw0 = (const float*)d_in[4];
    const float* tb0 = (const float*)d_in[5];
    const float* tw1 = (const float*)d_in[6];
    const float* tb1 = (const float*)d_in[7];
    const float* tw2 = (const float*)d_in[8];
    const float* tb2 = (const float*)d_in[9];
    const float* yw0 = (const float*)d_in[10];
    const float* yb0 = (const float*)d_in[11];
    const float* yw1 = (const float*)d_in[12];
    const float* yb1 = (const float*)d_in[13];
    const float* yhW = (const float*)d_in[14];
    const float* yhb = (const float*)d_in[15];
    const float* dw0 = (const float*)d_in[16];
    const float* db0 = (const float*)d_in[17];
    const float* dw1 = (const float*)d_in[18];
    const float* db1 = (const float*)d_in[19];
    const float* dhW = (const float*)d_in[20];
    const float* dhb = (const float*)d_in[21];
    const float* zw0 = (const float*)d_in[22];
    const float* zb0 = (const float*)d_in[23];
    const float* zw1 = (const float*)d_in[24];
    const float* zb1 = (const float*)d_in[25];
    const float* zhW = (const float*)d_in[26];
    const float* zhb = (const float*)d_in[27];
    float* out = (float*)d_out;

    __half *xh, *y1, *d1, *z1, *z2, *t1, *wh;
    float *fy, *fd, *ft;
    int *posmap;
    cudaGetSymbolAddress((void**)&xh, g_x);
    cudaGetSymbolAddress((void**)&y1, g_y1);
    cudaGetSymbolAddress((void**)&d1, g_d1);
    cudaGetSymbolAddress((void**)&z1, g_z1);
    cudaGetSymbolAddress((void**)&z2, g_z2);
    cudaGetSymbolAddress((void**)&t1, g_t1);
    cudaGetSymbolAddress((void**)&wh, g_wh);
    cudaGetSymbolAddress((void**)&fy, g_fy);
    cudaGetSymbolAddress((void**)&fd, g_fd);
    cudaGetSymbolAddress((void**)&ft, g_ft);
    cudaGetSymbolAddress((void**)&posmap, g_pos);

    static cudaStream_t s1, s2, s3;
    static cudaEvent_t eL1, eL2, eJ1, eJ2, eJ3;
    static bool init = false;
    if (!init) {
        cudaStreamCreateWithFlags(&s1, cudaStreamNonBlocking);
        cudaStreamCreateWithFlags(&s2, cudaStreamNonBlocking);
        cudaStreamCreateWithFlags(&s3, cudaStreamNonBlocking);
        cudaEventCreateWithFlags(&eL1, cudaEventDisableTiming);
        cudaEventCreateWithFlags(&eL2, cudaEventDisableTiming);
        cudaEventCreateWithFlags(&eJ1, cudaEventDisableTiming);
        cudaEventCreateWithFlags(&eJ2, cudaEventDisableTiming);
        cudaEventCreateWithFlags(&eJ3, cudaEventDisableTiming);
        cudaFuncSetAttribute((const void*)gemmT<true>,  cudaFuncAttributeMaxDynamicSharedMemorySize, SMEM_REQ);
        cudaFuncSetAttribute((const void*)gemmT<false>, cudaFuncAttributeMaxDynamicSharedMemorySize, SMEM_REQ);
        cudaFuncSetAttribute((const void*)gemmL1,       cudaFuncAttributeMaxDynamicSharedMemorySize, SMEM_REQ);
        cudaFuncSetAttribute((const void*)gemmL2,       cudaFuncAttributeMaxDynamicSharedMemorySize, SMEM_REQ);
        cudaFuncSetAttribute((const void*)zheadT,       cudaFuncAttributeMaxDynamicSharedMemorySize, SMEM_REQ);
        init = true;
    }

    static CUtensorMap M[12];
    make_map(&M[0],  xh, 1024, BATCH, 32, 256);
    make_map(&M[1],  y1, 1024, BATCH, 32, 256);
    make_map(&M[2],  d1, 1024, BATCH, 32, 256);
    make_map(&M[3],  z1, 1024, BATCH, 32, 256);
    make_map(&M[4],  z2, 1024, BATCH, 32, 256);
    make_map(&M[5],  t1, 256,  BATCH, 32, 256);
    make_map(&M[6],  wh + OFF_TW1, 256,  256,  32, 128);
    make_map(&M[7],  wh + OFF_L1,  1024, 3328, 32, 128);
    make_map(&M[8],  wh + OFF_YW1, 1024, 1024, 32, 128);
    make_map(&M[9],  wh + OFF_DW1, 1024, 1024, 32, 128);
    make_map(&M[10], wh + OFF_ZW1, 1024, 1024, 32, 128);
    make_map(&M[11], wh + OFF_ZHW, 1024, 3584, 32, 128);

    bucket_all<<<1, 1024>>>(t);
    xconv_kernel<<<(BATCH * 1024 + 255) / 256, 256>>>(x, xh, BATCH * 1024);
    WTab tab;
    tab.e[0]  = { tw1,            OFF_TW1,               256,  256 };
    tab.e[1]  = { yw0,            OFF_L1,                1024, 1024 };
    tab.e[2]  = { dw0,            OFF_L1 + 1048576ull,   1024, 1024 };
    tab.e[3]  = { zw0 + 2 * 1024, OFF_L1 + 2097152ull,   1024, 1024 };
    tab.e[4]  = { tw0,            OFF_L1 + 3145728ull,   1024, 256 };
    tab.e[5]  = { yw1,            OFF_YW1,               1024, 1024 };
    tab.e[6]  = { dw1,            OFF_DW1,               1024, 1024 };
    tab.e[7]  = { zw1,            OFF_ZW1,               1024, 1024 };
    for (int g = 0; g < 7; g++)
        tab.e[8 + g] = { zhW + (size_t)g * 1024 * 512,
                         (unsigned long long)(OFF_ZHW + (size_t)g * 524288), 1024, 512 };
    wconv_all<<<dim3(32, 32, 15), dim3(32, 8)>>>(tab, wh);

    // ---- L1 mega (y|d|z|t layer-1) ----
    L1Out O;
    O.o[0] = y1; O.bias[0] = yb0;
    O.o[1] = d1; O.bias[1] = db0;
    O.o[2] = z1; O.bias[2] = zb0;
    O.o[3] = t1; O.bias[3] = tb0;
    gemmL1<<<148, 512, SMEM_REQ>>>(M[0], M[7], O, yv, dv, zw0, posmap);
    cudaEventRecord(eL1, 0);

    // ---- L2 mega (y2 | d2 | z2) ----
    gemmL2<<<148, 512, SMEM_REQ>>>(M[1], M[2], M[3], M[8], M[9], M[10],
                                   yb1, db1, zb1, fy, fd, z2);
    cudaEventRecord(eL2, 0);

    const int headBlocks = (BATCH * 32) / 256;

    // ---- tails on streams ----
    cudaStreamWaitEvent(s1, eL1, 0);
    gemmT<true><<<128, 512, SMEM_REQ, s1>>>(M[5], M[6], tb1, 256, 256,
                                            ft, nullptr, 2, 128);
    thead_kernel<<<headBlocks, 256, 0, s1>>>(ft, tw2, tb2, out);
    cudaEventRecord(eJ1, s1);

    cudaStreamWaitEvent(s2, eL2, 0);
    head2_kernel<<<headBlocks, 256, 0, s2>>>(fy, t, yhW, yhb, out, 7);
    head2_kernel<<<headBlocks, 256, 0, s2>>>(fd, t, dhW, dhb, out, 9);
    cudaEventRecord(eJ2, s2);

    cudaStreamWaitEvent(s3, eL2, 0);
    zheadT<<<dim3(4, 64, 7), 512, SMEM_REQ, s3>>>(M[4], M[11], zhb, out);
    cudaEventRecord(eJ3, s3);

    cudaStreamWaitEvent(0, eJ1, 0);
    cudaStreamWaitEvent(0, eJ2, 0);
    cudaStreamWaitEvent(0, eJ3, 0);
}

// round 14
// speedup vs baseline: 2.1693x; 1.0928x over previous
#include <cuda_runtime.h>
#include <cuda.h>
#include <cuda_fp16.h>
#include <cstdint>
#include <math.h>

#define BATCH 16384
#define OUTC  523   // 7 + 4 + 512

// ========================= PTX helpers (baseline sm_90-level, no arch-suffix) =========================
__device__ __forceinline__ uint32_t smem_u32(const void* p) {
    uint32_t a;
    asm("{ .reg .u64 t; cvta.to.shared.u64 t, %1; cvt.u32.u64 %0, t; }" : "=r"(a) : "l"(p));
    return a;
}
__device__ __forceinline__ void ldmx4(uint32_t& r0, uint32_t& r1, uint32_t& r2, uint32_t& r3, uint32_t addr) {
    asm volatile("ldmatrix.sync.aligned.m8n8.x4.shared.b16 {%0,%1,%2,%3}, [%4];"
                 : "=r"(r0), "=r"(r1), "=r"(r2), "=r"(r3) : "r"(addr));
}
__device__ __forceinline__ void mma16816(float* c, const uint32_t* a, uint32_t b0, uint32_t b1) {
    asm volatile("mma.sync.aligned.m16n8k16.row.col.f32.f16.f16.f32 "
                 "{%0,%1,%2,%3}, {%4,%5,%6,%7}, {%8,%9}, {%0,%1,%2,%3};"
                 : "+f"(c[0]), "+f"(c[1]), "+f"(c[2]), "+f"(c[3])
                 : "r"(a[0]), "r"(a[1]), "r"(a[2]), "r"(a[3]), "r"(b0), "r"(b1));
}
// SW128 swizzle: atom = 8 rows x 128B; conflict-free ldmatrix for 128B-row tiles
__device__ __forceinline__ uint32_t swz128(uint32_t off) { return off ^ ((off >> 3) & 0x70); }

__device__ __forceinline__ void tma2d(uint32_t dst, const CUtensorMap* map, int cx, int cy, uint32_t mbar) {
    asm volatile("cp.async.bulk.tensor.2d.shared::cta.global.tile.mbarrier::complete_tx::bytes "
                 "[%0], [%1, {%2, %3}], [%4];"
                 :: "r"(dst), "l"(map), "r"(cx), "r"(cy), "r"(mbar) : "memory");
}
#define MBARRIER_INIT(addr, cnt) \
    asm volatile("mbarrier.init.shared.b64 [%0], %1;" :: "r"((uint32_t)(addr)), "r"((uint32_t)(cnt)) : "memory")
#define MBARRIER_ARRIVE(addr) \
    asm volatile("mbarrier.arrive.shared.b64 _, [%0];" :: "r"((uint32_t)(addr)) : "memory")
#define MBARRIER_EXPECT_TX(addr, bytes) \
    asm volatile("mbarrier.arrive.expect_tx.shared.b64 _, [%0], %1;" \
        :: "r"((uint32_t)(addr)), "r"((uint32_t)(bytes)) : "memory")
#define MBARRIER_WAIT_PARITY(mbar_smem_addr, phase_parity) do { \
    uint32_t _mbar = (uint32_t)(mbar_smem_addr); \
    uint32_t _parity = (uint32_t)(phase_parity); \
    uint32_t _done; \
    asm volatile("{\n\t.reg .pred p;\n\t" \
        "mbarrier.try_wait.parity.acquire.cta.shared::cta.b64 p, [%1], %2;\n\t" \
        "selp.b32 %0, 1, 0, p;\n\t}" : "=r"(_done) : "r"(_mbar), "r"(_parity) : "memory"); \
    if (!_done) { \
        asm volatile("{\n\t.reg .pred P1;\n\t" \
            "WAIT_LOOP_%=:\n\t" \
            "mbarrier.try_wait.parity.acquire.cta.shared::cta.b64 P1, [%0], %1, 0x989680;\n\t" \
            "@P1 bra.uni WAIT_DONE_%=;\n\t" \
            "bra.uni WAIT_LOOP_%=;\n\t" \
            "WAIT_DONE_%=:\n\t}" :: "r"(_mbar), "r"(_parity) : "memory"); \
    } \
} while(0)

// ========================= scratch =========================
__device__ __align__(1024) __half g_x[BATCH * 1024];
__device__ __align__(1024) __half g_y1[BATCH * 1024];
__device__ __align__(1024) __half g_d1[BATCH * 1024];
__device__ __align__(1024) __half g_z1[BATCH * 1024];   // bucket order
__device__ __align__(1024) __half g_z2[BATCH * 1024];   // bucket order
__device__ __align__(1024) __half g_t1[BATCH * 256];
__device__ float g_fy[BATCH * 1024];
__device__ float g_fd[BATCH * 1024];
__device__ float g_ft[BATCH * 256];
__device__ __align__(1024) __half g_wh[10300000];       // single-fp16 weight pool
__device__ int g_ridx[BATCH];
__device__ int g_pos[BATCH];
__device__ int g_cnt[8];
__device__ int g_off[8];

// weight-pool offsets (elements)
#define OFF_TW1 0             // [256,256]
#define OFF_L1  65536         // [3328,1024]: yw0|dw0|zw0'|tw0
#define OFF_YW1 3473408
#define OFF_DW1 4521984
#define OFF_ZW1 5570560
#define OFF_ZHW 6619136       // [3584,1024]

__device__ __forceinline__ float elu_f(float v) { return v > 0.f ? v : expm1f(v); }
__device__ __forceinline__ float softplus_f(float v) {
    return fmaxf(v, 0.f) + log1pf(expf(-fabsf(v)));
}

// ========================= fused bucketing =========================
__global__ void bucket_all(const int* __restrict__ t) {
    __shared__ int scnt[8];
    __shared__ int scur[8];
    int tid = threadIdx.x;
    if (tid < 8) scnt[tid] = 0;
    __syncthreads();
    for (int i = tid; i < BATCH; i += 1024) atomicAdd(&scnt[t[i]], 1);
    __syncthreads();
    if (tid == 0) {
        int s = 0;
        for (int k = 0; k < 7; k++) { g_cnt[k] = scnt[k]; g_off[k] = s; scur[k] = s; s += scnt[k]; }
    }
    __syncthreads();
    for (int i = tid; i < BATCH; i += 1024) {
        int p = atomicAdd(&scur[t[i]], 1);
        g_ridx[p] = i;
        g_pos[i] = p;
    }
}

// ========================= preprocessing =========================
__global__ void xconv_kernel(const float* __restrict__ x, __half* __restrict__ o, int n) {
    int i = (blockIdx.x * blockDim.x + threadIdx.x) * 2;
    if (i < n) {
        float2 v = *(const float2*)(x + i);
        __half2 h; h.x = __float2half(v.x); h.y = __float2half(v.y);
        *(__half2*)(o + i) = h;
    }
}
struct WEnt { const float* p; unsigned long long off; int kd, n; };
struct WTab { WEnt e[15]; };
__global__ void wconv_all(WTab tab, __half* __restrict__ wp) {
    WEnt E = tab.e[blockIdx.z];
    int n0 = blockIdx.x * 32, k0 = blockIdx.y * 32;
    if (n0 >= E.n || k0 >= E.kd) return;
    __shared__ float tile[32][33];
    int tx = threadIdx.x, ty = threadIdx.y;
    for (int i = ty; i < 32; i += 8)
        tile[i][tx] = E.p[(size_t)(k0 + i) * E.n + n0 + tx];
    __syncthreads();
    __half* W = wp + E.off;
    for (int i = ty; i < 32; i += 8)
        W[(size_t)(n0 + i) * E.kd + k0 + tx] = __float2half(tile[tx][i]);
}

// ========================= TMA-fed 1xFP16 mma.sync GEMM core =========================
// CTA tile 256x128, K-chunk 64 (128B rows, SW128), 512 threads = 16 warps, warp tile 64x32.
// Plain fp16 GEMM, fp32 accumulate. Persistent tile loop, 4 TMA stages.
#define S_A 0
#define S_B 32768
#define STAGE_SZ 49152
#define CHUNK_BYTES 49152u
#define NSTAGE 4
#define SMEM_REQ 198688

__device__ __forceinline__ void compute_chunk(uint32_t st, int warp_m, int warp_n, int lane,
                                              float acc[4][4][4])
{
    const int lrow = lane & 7;
    const int lmat = lane >> 3;
#pragma unroll
    for (int ks = 0; ks < 4; ks++) {
        uint32_t bw[8];
#pragma unroll
        for (int p = 0; p < 2; p++) {
            int ntile = p * 2 + (lmat >> 1);
            int half_ = lmat & 1;
            uint32_t off = (uint32_t)((warp_n * 32 + ntile * 8 + lrow) * 128 + (ks * 16 + half_ * 8) * 2);
            uint32_t a = swz128(off);
            ldmx4(bw[p * 4 + 0], bw[p * 4 + 1], bw[p * 4 + 2], bw[p * 4 + 3], st + S_B + a);
        }
#pragma unroll
        for (int mt = 0; mt < 4; mt++) {
            uint32_t ar[4];
            uint32_t off = (uint32_t)((warp_m * 64 + mt * 16 + (lmat & 1) * 8 + lrow) * 128
                                      + (ks * 16 + (lmat >> 1) * 8) * 2);
            uint32_t a = swz128(off);
            ldmx4(ar[0], ar[1], ar[2], ar[3], st + S_A + a);
#pragma unroll
            for (int nt = 0; nt < 4; nt++)
                mma16816(acc[mt][nt], ar, bw[nt * 2], bw[nt * 2 + 1]);
        }
    }
}

#define PERS_INIT()                                                              \
    if (tid == 0) {                                                              \
        for (int s = 0; s < NSTAGE; s++) {                                       \
            MBARRIER_INIT(mbar + s * 8, 1);                                      \
            MBARRIER_INIT(mbar + 32 + s * 8, 16);                                \
        }                                                                        \
    }                                                                            \
    __syncthreads();

#define PERS_ISSUE(PT, PK, STAGE)                                                \
    {                                                                            \
        uint32_t st_ = ab + (STAGE) * STAGE_SZ;                                  \
        uint32_t mb_ = mbar + (STAGE) * 8;                                       \
        int pbm_ = ((PT) / ntN) * 256, pbn_ = ((PT) % ntN) * 128;                \
        MBARRIER_EXPECT_TX(mb_, CHUNK_BYTES);                                    \
        tma2d(st_ + S_A, &tA, (PK) * 64, pbm_, mb_);                             \
        tma2d(st_ + S_B, &tB, (PK) * 64, pbn_, mb_);                             \
    }

// ---- persistent GEMM: C = elu(A@Wt^T + bias), output f32 or fp16 ----
template<bool OUT_F32>
__global__ void __launch_bounds__(512, 1)
gemmT(const __grid_constant__ CUtensorMap tA, const __grid_constant__ CUtensorMap tB,
      const float* __restrict__ bias, int N, int Kd,
      float* __restrict__ outF, __half* __restrict__ outH,
      int ntN, int nTiles)
{
    extern __shared__ char smraw[];
    uint32_t sb = smem_u32(smraw);
    uint32_t ab = (sb + 1023u) & ~1023u;
    const uint32_t mbar = ab + NSTAGE * STAGE_SZ;
    const int tid = threadIdx.x;
    const int wid = tid >> 5;
    const int lane = tid & 31;
    const int warp_m = wid & 3;
    const int warp_n = wid >> 2;
    const int nc = Kd >> 6;

    if (blockIdx.x >= (unsigned)nTiles) return;
    PERS_INIT()

    int tiles_mine = 0;
    for (int t = blockIdx.x; t < nTiles; t += gridDim.x) tiles_mine++;
    const long total = (long)tiles_mine * nc;

    int p_t = blockIdx.x, p_k = 0;
    if (tid == 0) {
        long lim = total < 3 ? total : 3;
        for (long i = 0; i < lim; i++) {
            PERS_ISSUE(p_t, p_k, (int)i)
            if (++p_k == nc) { p_k = 0; p_t += gridDim.x; }
        }
    }

    long g = 0;
    for (int t = blockIdx.x; t < nTiles; t += gridDim.x) {
        const int bm = (t / ntN) * 256, bn = (t % ntN) * 128;
        float acc[4][4][4];
#pragma unroll
        for (int i = 0; i < 4; i++)
#pragma unroll
            for (int j = 0; j < 4; j++)
#pragma unroll
                for (int q = 0; q < 4; q++) acc[i][j][q] = 0.f;

        for (int ch = 0; ch < nc; ch++, g++) {
            int s = (int)(g & 3);
            MBARRIER_WAIT_PARITY(mbar + s * 8, (int)((g >> 2) & 1));
            compute_chunk(ab + s * STAGE_SZ, warp_m, warp_n, lane, acc);
            if (lane == 0) MBARRIER_ARRIVE(mbar + 32 + s * 8);
            if (tid == 0) {
                long j = g + 3;
                if (j < total) {
                    int s3 = (int)(j & 3);
                    if (j >= 4) MBARRIER_WAIT_PARITY(mbar + 32 + s3 * 8, (int)(((j >> 2) - 1) & 1));
                    PERS_ISSUE(p_t, p_k, s3)
                    if (++p_k == nc) { p_k = 0; p_t += gridDim.x; }
                }
            }
        }

        const int tgm = lane >> 2;
        const int tgn = (lane & 3) * 2;
#pragma unroll
        for (int mt = 0; mt < 4; mt++) {
#pragma unroll
            for (int dh = 0; dh < 2; dh++) {
                int m = bm + warp_m * 64 + mt * 16 + tgm + dh * 8;
#pragma unroll
                for (int nt = 0; nt < 4; nt++) {
                    int n = bn + warp_n * 32 + nt * 8 + tgn;
                    float v0 = acc[mt][nt][dh * 2 + 0];
                    float v1 = acc[mt][nt][dh * 2 + 1];
                    float2 bb = *(const float2*)(bias + n);
                    v0 = elu_f(v0 + bb.x); v1 = elu_f(v1 + bb.y);
                    if (OUT_F32) {
                        *(float2*)(outF + (size_t)m * N + n) = make_float2(v0, v1);
                    } else {
                        __half2 hp; hp.x = __float2half(v0); hp.y = __float2half(v1);
                        *(__half2*)(outH + (size_t)m * N + n) = hp;
                    }
                }
            }
        }
    }
}

// ---- persistent batched layer-1 GEMM: N=3328 = [y|d|z|t] ----
struct L1Out {
    __half* o[4];
    const float* bias[4];
};
__global__ void __launch_bounds__(512, 1)
gemmL1(const __grid_constant__ CUtensorMap tA, const __grid_constant__ CUtensorMap tB,
       L1Out O, const float* __restrict__ yv, const float* __restrict__ dv,
       const float* __restrict__ wyd, const int* __restrict__ posmap)
{
    extern __shared__ char smraw[];
    uint32_t sb = smem_u32(smraw);
    uint32_t ab = (sb + 1023u) & ~1023u;
    const uint32_t mbar = ab + NSTAGE * STAGE_SZ;
    const int tid = threadIdx.x;
    const int wid = tid >> 5;
    const int lane = tid & 31;
    const int warp_m = wid & 3;
    const int warp_n = wid >> 2;
    const int nc = 16;
    const int ntN = 26;
    const int nTiles = 26 * 64;

    PERS_INIT()

    int tiles_mine = 0;
    for (int t = blockIdx.x; t < nTiles; t += gridDim.x) tiles_mine++;
    const long total = (long)tiles_mine * nc;

    int p_t = blockIdx.x, p_k = 0;
    if (tid == 0) {
        for (long i = 0; i < 3; i++) {
            PERS_ISSUE(p_t, p_k, (int)i)
            if (++p_k == nc) { p_k = 0; p_t += gridDim.x; }
        }
    }

    long g = 0;
    for (int t = blockIdx.x; t < nTiles; t += gridDim.x) {
        const int bm = (t / ntN) * 256;
        const int bnT = (t % ntN) * 128;
        const int seg = bnT >> 10;            // 0=y 1=d 2=z 3=t
        const int bn = bnT & 1023;
        float acc[4][4][4];
#pragma unroll
        for (int i = 0; i < 4; i++)
#pragma unroll
            for (int j = 0; j < 4; j++)
#pragma unroll
                for (int q = 0; q < 4; q++) acc[i][j][q] = 0.f;

        for (int ch = 0; ch < nc; ch++, g++) {
            int s = (int)(g & 3);
            MBARRIER_WAIT_PARITY(mbar + s * 8, (int)((g >> 2) & 1));
            compute_chunk(ab + s * STAGE_SZ, warp_m, warp_n, lane, acc);
            if (lane == 0) MBARRIER_ARRIVE(mbar + 32 + s * 8);
            if (tid == 0) {
                long j = g + 3;
                if (j < total) {
                    int s3 = (int)(j & 3);
                    if (j >= 4) MBARRIER_WAIT_PARITY(mbar + 32 + s3 * 8, (int)(((j >> 2) - 1) & 1));
                    PERS_ISSUE(p_t, p_k, s3)
                    if (++p_k == nc) { p_k = 0; p_t += gridDim.x; }
                }
            }
        }

        __half* oh = O.o[seg];
        const float* bias = O.bias[seg];
        const bool isZ = (seg == 2);
        const int segN = (seg == 3) ? 256 : 1024;
        const int tgm = lane >> 2;
        const int tgn = (lane & 3) * 2;
#pragma unroll
        for (int mt = 0; mt < 4; mt++) {
#pragma unroll
            for (int dh = 0; dh < 2; dh++) {
                int m = bm + warp_m * 64 + mt * 16 + tgm + dh * 8;
                float ya = 0.f, da = 0.f;
                int mo = m;
                if (isZ) { ya = __ldg(yv + m); da = __ldg(dv + m); mo = __ldg(posmap + m); }
#pragma unroll
                for (int nt = 0; nt < 4; nt++) {
                    int n = bn + warp_n * 32 + nt * 8 + tgn;
                    float v0 = acc[mt][nt][dh * 2 + 0];
                    float v1 = acc[mt][nt][dh * 2 + 1];
                    float2 bb = *(const float2*)(bias + n);
                    v0 += bb.x; v1 += bb.y;
                    if (isZ) {
                        float2 w0 = *(const float2*)(wyd + n);
                        float2 w1 = *(const float2*)(wyd + 1024 + n);
                        v0 += ya * w0.x + da * w1.x;
                        v1 += ya * w0.y + da * w1.y;
                    }
                    v0 = elu_f(v0); v1 = elu_f(v1);
                    __half2 hp; hp.x = __float2half(v0); hp.y = __float2half(v1);
                    *(__half2*)(oh + (size_t)mo * segN + n) = hp;
                }
            }
        }
    }
}

// ---- persistent merged layer-2 GEMM: 1536 tiles = 3 x 512 (y2, d2, z2) ----
__global__ void __launch_bounds__(512, 1)
gemmL2(const __grid_constant__ CUtensorMap tA0, const __grid_constant__ CUtensorMap tA1,
       const __grid_constant__ CUtensorMap tA2,
       const __grid_constant__ CUtensorMap tB0, const __grid_constant__ CUtensorMap tB1,
       const __grid_constant__ CUtensorMap tB2,
       const float* __restrict__ b0, const float* __restrict__ b1, const float* __restrict__ b2,
       float* __restrict__ fy, float* __restrict__ fd, __half* __restrict__ z2)
{
    extern __shared__ char smraw[];
    uint32_t sb = smem_u32(smraw);
    uint32_t ab = (sb + 1023u) & ~1023u;
    const uint32_t mbar = ab + NSTAGE * STAGE_SZ;
    const int tid = threadIdx.x;
    const int wid = tid >> 5;
    const int lane = tid & 31;
    const int warp_m = wid & 3;
    const int warp_n = wid >> 2;
    const int nc = 16;
    const int nTiles = 1536;

    const CUtensorMap* Am[3] = { &tA0, &tA1, &tA2 };
    const CUtensorMap* Bm[3] = { &tB0, &tB1, &tB2 };
    const float* biases[3] = { b0, b1, b2 };

    PERS_INIT()

    int tiles_mine = 0;
    for (int t = blockIdx.x; t < nTiles; t += gridDim.x) tiles_mine++;
    const long total = (long)tiles_mine * nc;

    auto issue = [&](int pt, int pk, int stage) {
        int seg_ = pt >> 9, ts_ = pt & 511;
        int bm_ = (ts_ >> 3) * 256, bn_ = (ts_ & 7) * 128;
        uint32_t st_ = ab + stage * STAGE_SZ;
        uint32_t mb_ = mbar + stage * 8;
        MBARRIER_EXPECT_TX(mb_, CHUNK_BYTES);
        tma2d(st_ + S_A, Am[seg_], pk * 64, bm_, mb_);
        tma2d(st_ + S_B, Bm[seg_], pk * 64, bn_, mb_);
    };

    int p_t = blockIdx.x, p_k = 0;
    if (tid == 0) {
        for (long i = 0; i < 3; i++) {
            issue(p_t, p_k, (int)i);
            if (++p_k == nc) { p_k = 0; p_t += gridDim.x; }
        }
    }

    long g = 0;
    for (int t = blockIdx.x; t < nTiles; t += gridDim.x) {
        const int seg = t >> 9, ts = t & 511;
        const int bm = (ts >> 3) * 256, bn = (ts & 7) * 128;
        float acc[4][4][4];
#pragma unroll
        for (int i = 0; i < 4; i++)
#pragma unroll
            for (int j = 0; j < 4; j++)
#pragma unroll
                for (int q = 0; q < 4; q++) acc[i][j][q] = 0.f;

        for (int ch = 0; ch < nc; ch++, g++) {
            int s = (int)(g & 3);
            MBARRIER_WAIT_PARITY(mbar + s * 8, (int)((g >> 2) & 1));
            compute_chunk(ab + s * STAGE_SZ, warp_m, warp_n, lane, acc);
            if (lane == 0) MBARRIER_ARRIVE(mbar + 32 + s * 8);
            if (tid == 0) {
                long j = g + 3;
                if (j < total) {
                    int s3 = (int)(j & 3);
                    if (j >= 4) MBARRIER_WAIT_PARITY(mbar + 32 + s3 * 8, (int)(((j >> 2) - 1) & 1));
                    issue(p_t, p_k, s3);
                    if (++p_k == nc) { p_k = 0; p_t += gridDim.x; }
                }
            }
        }

        const float* bias = biases[seg];
        const int tgm = lane >> 2;
        const int tgn = (lane & 3) * 2;
#pragma unroll
        for (int mt = 0; mt < 4; mt++) {
#pragma unroll
            for (int dh = 0; dh < 2; dh++) {
                int m = bm + warp_m * 64 + mt * 16 + tgm + dh * 8;
#pragma unroll
                for (int nt = 0; nt < 4; nt++) {
                    int n = bn + warp_n * 32 + nt * 8 + tgn;
                    float v0 = acc[mt][nt][dh * 2 + 0];
                    float v1 = acc[mt][nt][dh * 2 + 1];
                    float2 bb = *(const float2*)(bias + n);
                    v0 = elu_f(v0 + bb.x); v1 = elu_f(v1 + bb.y);
                    if (seg < 2) {
                        float* o = seg ? fd : fy;
                        *(float2*)(o + (size_t)m * 1024 + n) = make_float2(v0, v1);
                    } else {
                        __half2 hp; hp.x = __float2half(v0); hp.y = __float2half(v1);
                        *(__half2*)(z2 + (size_t)m * 1024 + n) = hp;
                    }
                }
            }
        }
    }
}

// ---- z head: grouped GEMM over gathered rows ----
__global__ void __launch_bounds__(512, 1)
zheadT(const __grid_constant__ CUtensorMap tA, const __grid_constant__ CUtensorMap tB,
       const float* __restrict__ zhb, float* __restrict__ out)
{
    const int grp = blockIdx.z;
    const int cnt = g_cnt[grp];
    const int m0 = blockIdx.y * 256;
    if (m0 >= cnt) return;
    const int base = g_off[grp];
    const int bn = blockIdx.x * 128;
    const int brow = grp * 512 + bn;
    const int arow = base + m0;

    extern __shared__ char smraw[];
    uint32_t sb = smem_u32(smraw);
    uint32_t ab = (sb + 1023u) & ~1023u;
    const uint32_t mbar = ab + NSTAGE * STAGE_SZ;
    const int tid = threadIdx.x;
    const int wid = tid >> 5;
    const int lane = tid & 31;
    const int warp_m = wid & 3;
    const int warp_n = wid >> 2;

    PERS_INIT()

    if (tid == 0) {
        for (int p = 0; p < 3; p++) {
            uint32_t st = ab + p * STAGE_SZ;
            uint32_t mb = mbar + p * 8;
            MBARRIER_EXPECT_TX(mb, CHUNK_BYTES);
            tma2d(st + S_A, &tA, p * 64, arow, mb);
            tma2d(st + S_B, &tB, p * 64, brow, mb);
        }
    }

    float acc[4][4][4];
#pragma unroll
    for (int i = 0; i < 4; i++)
#pragma unroll
        for (int j = 0; j < 4; j++)
#pragma unroll
            for (int q = 0; q < 4; q++) acc[i][j][q] = 0.f;

    for (int ch = 0; ch < 16; ch++) {
        int s = ch & 3;
        MBARRIER_WAIT_PARITY(mbar + s * 8, (ch >> 2) & 1);
        compute_chunk(ab + s * STAGE_SZ, warp_m, warp_n, lane, acc);
        if (lane == 0) MBARRIER_ARRIVE(mbar + 32 + s * 8);
        if (tid == 0 && ch + 3 < 16) {
            int s3 = (ch + 3) & 3;
            if (ch >= 1) MBARRIER_WAIT_PARITY(mbar + 32 + s3 * 8, (((ch + 3) >> 2) - 1) & 1);
            uint32_t st = ab + s3 * STAGE_SZ;
            uint32_t mb = mbar + s3 * 8;
            int k0 = (ch + 3) * 64;
            MBARRIER_EXPECT_TX(mb, CHUNK_BYTES);
            tma2d(st + S_A, &tA, k0, arow, mb);
            tma2d(st + S_B, &tB, k0, brow, mb);
        }
    }

    const int tgm = lane >> 2;
    const int tgn = (lane & 3) * 2;
#pragma unroll
    for (int mt = 0; mt < 4; mt++) {
#pragma unroll
        for (int dh = 0; dh < 2; dh++) {
            int mloc = warp_m * 64 + mt * 16 + tgm + dh * 8;
            int gi = m0 + mloc;
            if (gi >= cnt) continue;
            int rg = g_ridx[base + gi];
            float* op = out + (size_t)rg * OUTC + 11;
#pragma unroll
            for (int nt = 0; nt < 4; nt++) {
                int n = bn + warp_n * 32 + nt * 8 + tgn;
                float v0 = acc[mt][nt][dh * 2 + 0] + __ldg(zhb + grp * 512 + n);
                float v1 = acc[mt][nt][dh * 2 + 1] + __ldg(zhb + grp * 512 + n + 1);
                if (n < 256) {
                    v0 = fminf(fmaxf(v0, -100.f), 100.f);
                    v1 = fminf(fmaxf(v1, -100.f), 100.f);
                } else {
                    v0 = fminf(softplus_f(v0) + 0.001f, 100.f);
                    v1 = fminf(softplus_f(v1) + 0.001f, 100.f);
                }
                op[n] = v0;
                op[n + 1] = v1;
            }
        }
    }
}

// ========================= small head kernels (fp32) =========================
__global__ void thead_kernel(const float* __restrict__ hid, const float* __restrict__ tw2,
                             const float* __restrict__ tb2, float* __restrict__ out)
{
    int w = (blockIdx.x * blockDim.x + threadIdx.x) >> 5;
    int lane = threadIdx.x & 31;
    if (w >= BATCH) return;
    const float* hr = hid + (size_t)w * 256;
    float acc[7] = {0.f, 0.f, 0.f, 0.f, 0.f, 0.f, 0.f};
    for (int k = lane; k < 256; k += 32) {
        float h = hr[k];
        const float* wr = tw2 + k * 7;
#pragma unroll
        for (int j = 0; j < 7; j++) acc[j] = fmaf(h, wr[j], acc[j]);
    }
#pragma unroll
    for (int j = 0; j < 7; j++)
        for (int o = 16; o > 0; o >>= 1) acc[j] += __shfl_xor_sync(0xffffffffu, acc[j], o);
    if (lane == 0) {
#pragma unroll
        for (int j = 0; j < 7; j++) {
            float v = elu_f(acc[j] + tb2[j]);
            out[(size_t)w * OUTC + j] = fminf(fmaxf(v, -10.f), 10.f);
        }
    }
}
__global__ void head2_kernel(const float* __restrict__ hid, const int* __restrict__ t,
                             const float* __restrict__ hW, const float* __restrict__ hb,
                             float* __restrict__ out, int col0)
{
    int w = (blockIdx.x * blockDim.x + threadIdx.x) >> 5;
    int lane = threadIdx.x & 31;
    if (w >= BATCH) return;
    int tt = t[w];
    const float*  hr = hid + (size_t)w * 1024;
    const float2* wp = (const float2*)(hW + (size_t)tt * 2048);
    float a0 = 0.f, a1 = 0.f;
    for (int k = lane; k < 1024; k += 32) {
        float h = hr[k];
        float2 ww = wp[k];
        a0 = fmaf(h, ww.x, a0);
        a1 = fmaf(h, ww.y, a1);
    }
    for (int o = 16; o > 0; o >>= 1) {
        a0 += __shfl_xor_sync(0xffffffffu, a0, o);
        a1 += __shfl_xor_sync(0xffffffffu, a1, o);
    }
    if (lane == 0) {
        float loc = fminf(fmaxf(a0 + hb[tt * 2 + 0], -1e6f), 1e6f);
        float sc  = fminf(softplus_f(a1 + hb[tt * 2 + 1]) + 1e-3f, 1e6f);
        out[(size_t)w * OUTC + col0]     = loc;
        out[(size_t)w * OUTC + col0 + 1] = sc;
    }
}

// ========================= host-side tensormap builder =========================
typedef CUresult (*PFN_tmap)(CUtensorMap*, CUtensorMapDataType, cuuint32_t, void*,
                             const cuuint64_t*, const cuuint64_t*, const cuuint32_t*,
                             const cuuint32_t*, CUtensorMapInterleave, CUtensorMapSwizzle,
                             CUtensorMapL2promotion, CUtensorMapFloatOOBfill);
static PFN_tmap tmap_fn() {
    static PFN_tmap fn = nullptr;
    if (!fn) {
        cudaDriverEntryPointQueryResult qr;
        cudaGetDriverEntryPointByVersion("cuTensorMapEncodeTiled", (void**)&fn, 12000,
                                         cudaEnableDefault, &qr);
    }
    return fn;
}
static void make_map(CUtensorMap* m, const __half* base, unsigned long long inner,
                     unsigned long long outer, unsigned box_in, unsigned box_out) {
    cuuint64_t dims[2] = { inner, outer };
    cuuint64_t strides[1] = { inner * 2 };
    cuuint32_t box[2] = { box_in, box_out };
    cuuint32_t es[2] = { 1, 1 };
    tmap_fn()(m, CU_TENSOR_MAP_DATA_TYPE_FLOAT16, 2, (void*)base, dims, strides, box, es,
              CU_TENSOR_MAP_INTERLEAVE_NONE, CU_TENSOR_MAP_SWIZZLE_128B,
              CU_TENSOR_MAP_L2_PROMOTION_L2_128B, CU_TENSOR_MAP_FLOAT_OOB_FILL_NONE);
}

// ========================= launch =========================
extern "C" void kernel_launch(void* const* d_in, const int* in_sizes, int n_in,
                              void* d_out, int out_size)
{
    const float* x   = (const float*)d_in[0];
    const int*   t   = (const int*)  d_in[1];
    const float* yv  = (const float*)d_in[2];
    const float* dv  = (const float*)d_in[3];
    const float* tw0 = (const float*)d_in[4];
    const float* tb0 = (const float*)d_in[5];
    const float* tw1 = (const float*)d_in[6];
    const float* tb1 = (const float*)d_in[7];
    const float* tw2 = (const float*)d_in[8];
    const float* tb2 = (const float*)d_in[9];
    const float* yw0 = (const float*)d_in[10];
    const float* yb0 = (const float*)d_in[11];
    const float* yw1 = (const float*)d_in[12];
    const float* yb1 = (const float*)d_in[13];
    const float* yhW = (const float*)d_in[14];
    const float* yhb = (const float*)d_in[15];
    const float* dw0 = (const float*)d_in[16];
    const float* db0 = (const float*)d_in[17];
    const float* dw1 = (const float*)d_in[18];
    const float* db1 = (const float*)d_in[19];
    const float* dhW = (const float*)d_in[20];
    const float* dhb = (const float*)d_in[21];
    const float* zw0 = (const float*)d_in[22];
    const float* zb0 = (const float*)d_in[23];
    const float* zw1 = (const float*)d_in[24];
    const float* zb1 = (const float*)d_in[25];
    const float* zhW = (const float*)d_in[26];
    const float* zhb = (const float*)d_in[27];
    float* out = (float*)d_out;

    __half *xh, *y1, *d1, *z1, *z2, *t1, *wh;
    float *fy, *fd, *ft;
    int *posmap;
    cudaGetSymbolAddress((void**)&xh, g_x);
    cudaGetSymbolAddress((void**)&y1, g_y1);
    cudaGetSymbolAddress((void**)&d1, g_d1);
    cudaGetSymbolAddress((void**)&z1, g_z1);
    cudaGetSymbolAddress((void**)&z2, g_z2);
    cudaGetSymbolAddress((void**)&t1, g_t1);
    cudaGetSymbolAddress((void**)&wh, g_wh);
    cudaGetSymbolAddress((void**)&fy, g_fy);
    cudaGetSymbolAddress((void**)&fd, g_fd);
    cudaGetSymbolAddress((void**)&ft, g_ft);
    cudaGetSymbolAddress((void**)&posmap, g_pos);

    static cudaStream_t s1, s2, s3;
    static cudaEvent_t eL1, eL2, eJ1, eJ2, eJ3;
    static bool init = false;
    if (!init) {
        cudaStreamCreateWithFlags(&s1, cudaStreamNonBlocking);
        cudaStreamCreateWithFlags(&s2, cudaStreamNonBlocking);
        cudaStreamCreateWithFlags(&s3, cudaStreamNonBlocking);
        cudaEventCreateWithFlags(&eL1, cudaEventDisableTiming);
        cudaEventCreateWithFlags(&eL2, cudaEventDisableTiming);
        cudaEventCreateWithFlags(&eJ1, cudaEventDisableTiming);
        cudaEventCreateWithFlags(&eJ2, cudaEventDisableTiming);
        cudaEventCreateWithFlags(&eJ3, cudaEventDisableTiming);
        cudaFuncSetAttribute((const void*)gemmT<true>,  cudaFuncAttributeMaxDynamicSharedMemorySize, SMEM_REQ);
        cudaFuncSetAttribute((const void*)gemmT<false>, cudaFuncAttributeMaxDynamicSharedMemorySize, SMEM_REQ);
        cudaFuncSetAttribute((const void*)gemmL1,       cudaFuncAttributeMaxDynamicSharedMemorySize, SMEM_REQ);
        cudaFuncSetAttribute((const void*)gemmL2,       cudaFuncAttributeMaxDynamicSharedMemorySize, SMEM_REQ);
        cudaFuncSetAttribute((const void*)zheadT,       cudaFuncAttributeMaxDynamicSharedMemorySize, SMEM_REQ);
        init = true;
    }

    static CUtensorMap M[12];
    make_map(&M[0],  xh, 1024, BATCH, 64, 256);
    make_map(&M[1],  y1, 1024, BATCH, 64, 256);
    make_map(&M[2],  d1, 1024, BATCH, 64, 256);
    make_map(&M[3],  z1, 1024, BATCH, 64, 256);
    make_map(&M[4],  z2, 1024, BATCH, 64, 256);
    make_map(&M[5],  t1, 256,  BATCH, 64, 256);
    make_map(&M[6],  wh + OFF_TW1, 256,  256,  64, 128);
    make_map(&M[7],  wh + OFF_L1,  1024, 3328, 64, 128);
    make_map(&M[8],  wh + OFF_YW1, 1024, 1024, 64, 128);
    make_map(&M[9],  wh + OFF_DW1, 1024, 1024, 64, 128);
    make_map(&M[10], wh + OFF_ZW1, 1024, 1024, 64, 128);
    make_map(&M[11], wh + OFF_ZHW, 1024, 3584, 64, 128);

    bucket_all<<<1, 1024>>>(t);
    xconv_kernel<<<(BATCH * 1024 / 2 + 255) / 256, 256>>>(x, xh, BATCH * 1024);
    WTab tab;
    tab.e[0]  = { tw1,            OFF_TW1,               256,  256 };
    tab.e[1]  = { yw0,            OFF_L1,                1024, 1024 };
    tab.e[2]  = { dw0,            OFF_L1 + 1048576ull,   1024, 1024 };
    tab.e[3]  = { zw0 + 2 * 1024, OFF_L1 + 2097152ull,   1024, 1024 };
    tab.e[4]  = { tw0,            OFF_L1 + 3145728ull,   1024, 256 };
    tab.e[5]  = { yw1,            OFF_YW1,               1024, 1024 };
    tab.e[6]  = { dw1,            OFF_DW1,               1024, 1024 };
    tab.e[7]  = { zw1,            OFF_ZW1,               1024, 1024 };
    for (int g = 0; g < 7; g++)
        tab.e[8 + g] = { zhW + (size_t)g * 1024 * 512,
                         (unsigned long long)(OFF_ZHW + (size_t)g * 524288), 1024, 512 };
    wconv_all<<<dim3(32, 32, 15), dim3(32, 8)>>>(tab, wh);

    // ---- L1 mega (y|d|z|t layer-1) ----
    L1Out O;
    O.o[0] = y1; O.bias[0] = yb0;
    O.o[1] = d1; O.bias[1] = db0;
    O.o[2] = z1; O.bias[2] = zb0;
    O.o[3] = t1; O.bias[3] = tb0;
    gemmL1<<<148, 512, SMEM_REQ>>>(M[0], M[7], O, yv, dv, zw0, posmap);
    cudaEventRecord(eL1, 0);

    // ---- L2 mega (y2 | d2 | z2) ----
    gemmL2<<<148, 512, SMEM_REQ>>>(M[1], M[2], M[3], M[8], M[9], M[10],
                                   yb1, db1, zb1, fy, fd, z2);
    cudaEventRecord(eL2, 0);

    const int headBlocks = (BATCH * 32) / 256;

    // ---- tails on streams ----
    cudaStreamWaitEvent(s1, eL1, 0);
    gemmT<true><<<128, 512, SMEM_REQ, s1>>>(M[5], M[6], tb1, 256, 256,
                                            ft, nullptr, 2, 128);
    thead_kernel<<<headBlocks, 256, 0, s1>>>(ft, tw2, tb2, out);
    cudaEventRecord(eJ1, s1);

    cudaStreamWaitEvent(s2, eL2, 0);
    head2_kernel<<<headBlocks, 256, 0, s2>>>(fy, t, yhW, yhb, out, 7);
    head2_kernel<<<headBlocks, 256, 0, s2>>>(fd, t, dhW, dhb, out, 9);
    cudaEventRecord(eJ2, s2);

    cudaStreamWaitEvent(s3, eL2, 0);
    zheadT<<<dim3(4, 64, 7), 512, SMEM_REQ, s3>>>(M[4], M[11], zhb, out);
    cudaEventRecord(eJ3, s3);

    cudaStreamWaitEvent(0, eJ1, 0);
    cudaStreamWaitEvent(0, eJ2, 0);
    cudaStreamWaitEvent(0, eJ3, 0);
}